// round 7
// baseline (speedup 1.0000x reference)
#include <cuda_runtime.h>
#include <cuda_bf16.h>
#include <math.h>

#define B_   64
#define S_   4096
#define DEC_ 512
#define ENC_ 256
#define MT   64                                        // rows per k_scores tile

// ---------------- device scratch (allocation-free rule) ----------------
__device__ float2 g_dw[B_ * ENC_];                    // (dpe, Wa) per (b,f)
__device__ float  g_scores[B_ * S_];
__device__ float  g_cpart[8 * B_ * ENC_];
// We^T bf16 hi/lo per K-chunk, LDSM-native block layout:
//   block (g,ks) = 512B of 32 x 16B slices; slice holds rows n=g*16..+15, k-halves
//   addr(n,kc) = (g*2+ks)*512 + h16*256 + (n&15)*16 + (kc&7)*2
__device__ __align__(16) unsigned char g_Bt[2][8][16384];

// ---------------- smem layout (bytes), per CTA = 92160 ----------------
#define OBI(buf, hl) ((unsigned)(buf) * 32768u + (unsigned)(hl) * 16384u)       // 64K
#define OAI(buf, hl) (65536u + (unsigned)(buf) * 8192u + (unsigned)(hl) * 4096u) // 16K
#define OSTG         81920u                            // fp32 stage [64][128B] (reused: red)
#define ODW          90112u                            // float2[256]
#define SMEM_BYTES   92160u

static __device__ __forceinline__ unsigned s2u(const void* p) {
    unsigned a;
    asm("{ .reg .u64 t; cvta.to.shared.u64 t, %1; cvt.u32.u64 %0, t; }" : "=r"(a) : "l"(p));
    return a;
}
static __device__ __forceinline__ void cp16(unsigned dst, const void* src) {
    asm volatile("cp.async.cg.shared.global [%0], [%1], 16;" :: "r"(dst), "l"(src));
}
static __device__ __forceinline__ void cp16ca(unsigned dst, const void* src) {
    asm volatile("cp.async.ca.shared.global [%0], [%1], 16;" :: "r"(dst), "l"(src));
}
#define CP_COMMIT() asm volatile("cp.async.commit_group;" ::: "memory")
#define CP_WAIT0()  asm volatile("cp.async.wait_group 0;" ::: "memory")

#define LDM4(r, addr) \
    asm volatile("ldmatrix.sync.aligned.m8n8.x4.shared.b16 {%0,%1,%2,%3}, [%4];" \
        : "=r"((r)[0]), "=r"((r)[1]), "=r"((r)[2]), "=r"((r)[3]) : "r"(addr))

#define MMA(d, a, b0, b1) \
    asm volatile("mma.sync.aligned.m16n8k16.row.col.f32.bf16.bf16.f32 " \
        "{%0,%1,%2,%3}, {%4,%5,%6,%7}, {%8,%9}, {%0,%1,%2,%3};" \
        : "+f"((d)[0]), "+f"((d)[1]), "+f"((d)[2]), "+f"((d)[3]) \
        : "r"((a)[0]), "r"((a)[1]), "r"((a)[2]), "r"((a)[3]), "r"(b0), "r"(b1))

static __device__ __forceinline__ float tanh_fast(float x) {
    float e = __expf(x + x);
    return 1.f - __fdividef(2.f, e + 1.f);
}

// ---------------------------------------------------------------------------
// Prep: We^T -> bf16 hi/lo chunk images in LDSM-native block layout
// ---------------------------------------------------------------------------
__global__ void k_prep(const float* __restrict__ We) {
    int k = blockIdx.x, n = threadIdx.x;
    float v = We[k * 256 + n];
    __nv_bfloat16 h = __float2bfloat16_rn(v);
    __nv_bfloat16 l = __float2bfloat16_rn(v - __bfloat162float(h));
    int ch = k >> 5, kc = k & 31;
    int g = n >> 4, ks = kc >> 4, h16 = (kc >> 3) & 1;
    unsigned addr = (unsigned)((g * 2 + ks) * 512 + h16 * 256 + (n & 15) * 16 + (kc & 7) * 2);
    *(__nv_bfloat16*)&g_Bt[0][ch][addr] = h;
    *(__nv_bfloat16*)&g_Bt[1][ch][addr] = l;
}

// ---------------------------------------------------------------------------
// dpe[b,f] = dh[b,:]@Wd[:,f] + bd + be, paired with Wa
// ---------------------------------------------------------------------------
__global__ void k_decproj(const float* __restrict__ dh, const float* __restrict__ Wd,
                          const float* __restrict__ bd, const float* __restrict__ be,
                          const float* __restrict__ Wa) {
    int b = blockIdx.x, f = threadIdx.x;
    __shared__ float sdh[DEC_];
    for (int d = f; d < DEC_; d += ENC_) sdh[d] = dh[b * DEC_ + d];
    __syncthreads();
    float acc = bd[f] + be[f];
#pragma unroll 8
    for (int d = 0; d < DEC_; ++d) acc += sdh[d] * Wd[d * ENC_ + f];
    g_dw[b * ENC_ + f] = make_float2(acc, Wa[f]);
}

// ---------------------------------------------------------------------------
// k_scores: 64x256 tile, 256 thr, 2 CTAs/SM; bf16x3-split HMMA + tanh*Wa
// ---------------------------------------------------------------------------
static __device__ __forceinline__ void load_chunk(unsigned sb, const float* __restrict__ enc,
                                                  int row0, int c) {
    const int tid = threadIdx.x;
    const int buf = c & 1;
#pragma unroll
    for (int i = 0; i < 2; ++i) {                     // A stage: 512 float4 (single buf)
        int idx = tid + i * 256;
        int r = idx >> 3, seg = idx & 7;
        int unit = (((seg >> 1) ^ (r & 3)) << 1) + (seg & 1);
        cp16(sb + OSTG + (unsigned)r * 128u + (unsigned)unit * 16u,
             enc + (size_t)(row0 + r) * 256 + c * 32 + seg * 4);
    }
#pragma unroll
    for (int i = 0; i < 8; ++i) {                     // B images: 2048 x 16B, contiguous
        int u = tid + i * 256;
        int hl = u >> 10, slot = u & 1023;
        cp16ca(sb + OBI(buf, hl) + (unsigned)slot * 16u, &g_Bt[hl][c][slot * 16]);
    }
    CP_COMMIT();
}

__global__ __launch_bounds__(256, 2)
void k_scores(const float* __restrict__ enc) {
    extern __shared__ __align__(16) unsigned char sm[];
    const unsigned sb = s2u(sm);
    const int tid = threadIdx.x, lane = tid & 31, w = tid >> 5;
    const int wr = w & 1, wc = w >> 1;                // 2 row-groups x 4 col-groups
    const int row0 = blockIdx.x * MT, b = row0 >> 12;

    load_chunk(sb, enc, row0, 0);
    ((float2*)(sm + ODW))[tid] = g_dw[b * 256 + tid];

    float acc[2][8][4];
#pragma unroll
    for (int mi = 0; mi < 2; ++mi)
#pragma unroll
        for (int ni = 0; ni < 8; ++ni)
#pragma unroll
            for (int q = 0; q < 4; ++q) acc[mi][ni][q] = 0.f;

    // per-lane ldmatrix offsets within a 512B block (LDSM-native layout)
    const unsigned a_lo = (unsigned)((lane & 15) * 16 + (lane >> 4) * 256);
    const unsigned b_lo = (unsigned)((lane & 7) * 16 + ((lane >> 4) & 1) * 128 +
                                     ((lane >> 3) & 1) * 256);

#pragma unroll 1
    for (int c = 0; c < 8; ++c) {
        const int buf = c & 1;
        CP_WAIT0();
        __syncthreads();
        // convert fp32 stage -> bf16 hi/lo images (8 floats / thread)
        {
            int r = tid >> 2, s = tid & 3;
            int pch = s ^ (r & 3);
            const float4* s4 = (const float4*)(sm + OSTG + (unsigned)r * 128u +
                                               (unsigned)pch * 32u);
            float4 v0 = s4[0], v1 = s4[1];
            float vf[8] = {v0.x, v0.y, v0.z, v0.w, v1.x, v1.y, v1.z, v1.w};
            unsigned hu[4], lu[4];
#pragma unroll
            for (int q = 0; q < 4; ++q) {
                __nv_bfloat16 h0 = __float2bfloat16_rn(vf[2 * q]);
                __nv_bfloat16 h1 = __float2bfloat16_rn(vf[2 * q + 1]);
                __nv_bfloat162 hp = __halves2bfloat162(h0, h1);
                __nv_bfloat162 lp = __halves2bfloat162(
                    __float2bfloat16_rn(vf[2 * q] - __bfloat162float(h0)),
                    __float2bfloat16_rn(vf[2 * q + 1] - __bfloat162float(h1)));
                hu[q] = *(unsigned*)&hp;
                lu[q] = *(unsigned*)&lp;
            }
            int g = r >> 4, ks = s >> 1, h16 = s & 1;
            unsigned doff = (unsigned)((g * 2 + ks) * 512 + h16 * 256 + (r & 15) * 16);
            asm volatile("st.shared.v4.b32 [%0], {%1,%2,%3,%4};"
                         :: "r"(sb + OAI(buf, 0) + doff),
                            "r"(hu[0]), "r"(hu[1]), "r"(hu[2]), "r"(hu[3]));
            asm volatile("st.shared.v4.b32 [%0], {%1,%2,%3,%4};"
                         :: "r"(sb + OAI(buf, 1) + doff),
                            "r"(lu[0]), "r"(lu[1]), "r"(lu[2]), "r"(lu[3]));
        }
        __syncthreads();
        if (c < 7) load_chunk(sb, enc, row0, c + 1);  // overlaps MMA below

        const unsigned ah_b = sb + OAI(buf, 0) + a_lo, al_b = sb + OAI(buf, 1) + a_lo;
        const unsigned bh_b = sb + OBI(buf, 0) + b_lo, bl_b = sb + OBI(buf, 1) + b_lo;
#pragma unroll
        for (int ks = 0; ks < 2; ++ks) {
            unsigned af[2][4], bh[8][2], bl[8][2];
#pragma unroll
            for (int mi = 0; mi < 2; ++mi)
                LDM4(af[mi], ah_b + (unsigned)(((wr * 2 + mi) * 2 + ks) * 512));
#pragma unroll
            for (int p = 0; p < 4; ++p) {
                const unsigned blk = (unsigned)(((wc * 4 + p) * 2 + ks) * 512);
                unsigned r4[4];
                LDM4(r4, bh_b + blk);
                bh[2 * p][0] = r4[0]; bh[2 * p][1] = r4[1];
                bh[2 * p + 1][0] = r4[2]; bh[2 * p + 1][1] = r4[3];
                LDM4(r4, bl_b + blk);
                bl[2 * p][0] = r4[0]; bl[2 * p][1] = r4[1];
                bl[2 * p + 1][0] = r4[2]; bl[2 * p + 1][1] = r4[3];
            }
#pragma unroll
            for (int mi = 0; mi < 2; ++mi)
#pragma unroll
                for (int ni = 0; ni < 8; ++ni) {
                    MMA(acc[mi][ni], af[mi], bh[ni][0], bh[ni][1]);
                    MMA(acc[mi][ni], af[mi], bl[ni][0], bl[ni][1]);
                }
#pragma unroll
            for (int mi = 0; mi < 2; ++mi)            // reuse af regs for A_lo
                LDM4(af[mi], al_b + (unsigned)(((wr * 2 + mi) * 2 + ks) * 512));
#pragma unroll
            for (int mi = 0; mi < 2; ++mi)
#pragma unroll
                for (int ni = 0; ni < 8; ++ni)
                    MMA(acc[mi][ni], af[mi], bh[ni][0], bh[ni][1]);
        }
    }

    // Epilogue: partial scores = sum_cols Wa * tanh(dpe + v); red reuses stage
    const float2* sdw = (const float2*)(sm + ODW);
    float* red = (float*)(sm + OSTG);                 // [64][5] padded
#pragma unroll
    for (int mi = 0; mi < 2; ++mi) {
        float p0 = 0.f, p1 = 0.f;
#pragma unroll
        for (int ni = 0; ni < 8; ++ni) {
            int cc = wc * 64 + ni * 8 + 2 * (lane & 3);
            float2 w0 = sdw[cc], w1 = sdw[cc + 1];
            p0 += w0.y * tanh_fast(acc[mi][ni][0] + w0.x) +
                  w1.y * tanh_fast(acc[mi][ni][1] + w1.x);
            p1 += w0.y * tanh_fast(acc[mi][ni][2] + w0.x) +
                  w1.y * tanh_fast(acc[mi][ni][3] + w1.x);
        }
        p0 += __shfl_xor_sync(~0u, p0, 1); p0 += __shfl_xor_sync(~0u, p0, 2);
        p1 += __shfl_xor_sync(~0u, p1, 1); p1 += __shfl_xor_sync(~0u, p1, 2);
        if ((lane & 3) == 0) {
            int r = wr * 32 + mi * 16 + (lane >> 2);
            red[r * 5 + wc] = p0;
            red[(r + 8) * 5 + wc] = p1;
        }
    }
    __syncthreads();
    if (tid < MT) {
        float s = red[tid * 5] + red[tid * 5 + 1] + red[tid * 5 + 2] + red[tid * 5 + 3];
        g_scores[row0 + tid] = s;
    }
}

// ---------------------------------------------------------------------------
// Masked softmax over S per batch
// ---------------------------------------------------------------------------
__global__ void k_softmax(const int* __restrict__ mask, float* __restrict__ attn) {
    const int b = blockIdx.x, t = threadIdx.x;
    const float* sc = g_scores + b * S_;
    const int* mk = mask + b * S_;
    float v[4], mx = -INFINITY;
#pragma unroll
    for (int i = 0; i < 4; ++i) {
        int s = t + i * 1024;
        float x = (mk[s] == 0) ? -1e10f : sc[s];
        v[i] = x; mx = fmaxf(mx, x);
    }
    __shared__ float rb[32];
    for (int o = 16; o; o >>= 1) mx = fmaxf(mx, __shfl_xor_sync(~0u, mx, o));
    if ((t & 31) == 0) rb[t >> 5] = mx;
    __syncthreads();
    if (t < 32) {
        float m2 = rb[t];
        for (int o = 16; o; o >>= 1) m2 = fmaxf(m2, __shfl_xor_sync(~0u, m2, o));
        rb[t] = m2;
    }
    __syncthreads();
    mx = rb[0];
    __syncthreads();
    float e[4], tot = 0.f;
#pragma unroll
    for (int i = 0; i < 4; ++i) { e[i] = expf(v[i] - mx); tot += e[i]; }
    for (int o = 16; o; o >>= 1) tot += __shfl_xor_sync(~0u, tot, o);
    if ((t & 31) == 0) rb[t >> 5] = tot;
    __syncthreads();
    if (t < 32) {
        float s2 = rb[t];
        for (int o = 16; o; o >>= 1) s2 += __shfl_xor_sync(~0u, s2, o);
        rb[t] = s2;
    }
    __syncthreads();
    const float inv = 1.f / rb[0];
#pragma unroll
    for (int i = 0; i < 4; ++i) attn[b * S_ + t + i * 1024] = e[i] * inv;
}

// ---------------------------------------------------------------------------
// Context: split S over 8 segments (512 CTAs) + reduce
// ---------------------------------------------------------------------------
__global__ void k_context(const float* __restrict__ enc, const float* __restrict__ attn) {
    const int seg = blockIdx.x & 7, b = blockIdx.x >> 3, t = threadIdx.x;
    const int c4 = t & 63, sg = t >> 6;
    const float4* e4 = (const float4*)enc + (size_t)b * S_ * 64;
    const float* at = attn + b * S_;
    float4 acc = make_float4(0.f, 0.f, 0.f, 0.f);
    const int s0 = seg * 512;
#pragma unroll 4
    for (int s = s0 + sg; s < s0 + 512; s += 4) {
        float a = at[s];
        float4 e = e4[(size_t)s * 64 + c4];
        acc.x += a * e.x; acc.y += a * e.y; acc.z += a * e.z; acc.w += a * e.w;
    }
    __shared__ float4 sr[4][64];
    sr[sg][c4] = acc;
    __syncthreads();
    if (t < 64) {
        float4 r = sr[0][t];
#pragma unroll
        for (int g = 1; g < 4; ++g) {
            float4 q = sr[g][t];
            r.x += q.x; r.y += q.y; r.z += q.z; r.w += q.w;
        }
        ((float4*)g_cpart)[(b * 8 + seg) * 64 + t] = r;
    }
}
__global__ void k_cred(float* __restrict__ ctx) {
    const int b = blockIdx.x, t = threadIdx.x;
    const float4* p = (const float4*)g_cpart;
    float4 r = make_float4(0.f, 0.f, 0.f, 0.f);
#pragma unroll
    for (int seg = 0; seg < 8; ++seg) {
        float4 q = p[(b * 8 + seg) * 64 + t];
        r.x += q.x; r.y += q.y; r.z += q.z; r.w += q.w;
    }
    ((float4*)ctx)[b * 64 + t] = r;
}

// ---------------------------------------------------------------------------
extern "C" void kernel_launch(void* const* d_in, const int* in_sizes, int n_in,
                              void* d_out, int out_size) {
    const float* dh   = (const float*)d_in[0];
    const float* enc  = (const float*)d_in[1];
    const int*   mask = (const int*)  d_in[2];
    const float* Wd   = (const float*)d_in[3];
    const float* bd   = (const float*)d_in[4];
    const float* We   = (const float*)d_in[5];
    const float* be   = (const float*)d_in[6];
    const float* Wa   = (const float*)d_in[7];
    // d_in[8] = ba: uniform shift on scores, cancels in softmax

    float* out  = (float*)d_out;
    float* ctx  = out;
    float* attn = out + B_ * ENC_;

    cudaFuncSetAttribute(k_scores, cudaFuncAttributeMaxDynamicSharedMemorySize, SMEM_BYTES);

    k_prep<<<256, 256>>>(We);
    k_decproj<<<B_, ENC_>>>(dh, Wd, bd, be, Wa);
    k_scores<<<(B_ * S_) / MT, 256, SMEM_BYTES>>>(enc);
    k_softmax<<<B_, 1024>>>(mask, attn);
    k_context<<<8 * B_, 256>>>(enc, attn);
    k_cred<<<B_, 64>>>(ctx);
}

// round 8
// speedup vs baseline: 1.3208x; 1.3208x over previous
#include <cuda_runtime.h>
#include <cuda_fp16.h>
#include <math.h>

#define B_   64
#define S_   4096
#define DEC_ 512
#define ENC_ 256
#define MT   64                                        // rows per k_scores tile

// ---------------- device scratch (allocation-free rule) ----------------
__device__ float2 g_dw[B_ * ENC_];                    // (dpe, Wa) per (b,f)
__device__ float  g_scores[B_ * S_];
__device__ float  g_cpart[8 * B_ * ENC_];
// We^T fp16 (single precision level) per K-chunk, LDSM-native block layout:
//   addr(n,kc) = (g*2+ks)*512 + h16*256 + (n&15)*16 + (kc&7)*2,
//   g=n>>4, ks=kc>>4, h16=(kc>>3)&1
__device__ __align__(16) unsigned char g_Bt[8][16384];

// ---------------- smem layout (bytes), per CTA = 59392 ----------------
#define OBI(buf)     ((unsigned)(buf) * 16384u)        // B fp16, 32K dbuf
#define OAI(buf, hl) (32768u + (unsigned)(buf) * 8192u + (unsigned)(hl) * 4096u) // A hi/lo
#define OSTG         49152u                            // fp32 stage [64][128B] (reused: red)
#define ODW          57344u                            // float2[256]
#define SMEM_BYTES   59392u

static __device__ __forceinline__ unsigned s2u(const void* p) {
    unsigned a;
    asm("{ .reg .u64 t; cvta.to.shared.u64 t, %1; cvt.u32.u64 %0, t; }" : "=r"(a) : "l"(p));
    return a;
}
static __device__ __forceinline__ void cp16(unsigned dst, const void* src) {
    asm volatile("cp.async.cg.shared.global [%0], [%1], 16;" :: "r"(dst), "l"(src));
}
#define CP_COMMIT() asm volatile("cp.async.commit_group;" ::: "memory")
#define CP_WAIT0()  asm volatile("cp.async.wait_group 0;" ::: "memory")

#define LDM4(r, addr) \
    asm volatile("ldmatrix.sync.aligned.m8n8.x4.shared.b16 {%0,%1,%2,%3}, [%4];" \
        : "=r"((r)[0]), "=r"((r)[1]), "=r"((r)[2]), "=r"((r)[3]) : "r"(addr))

#define MMAH(d, a, b0, b1) \
    asm volatile("mma.sync.aligned.m16n8k16.row.col.f32.f16.f16.f32 " \
        "{%0,%1,%2,%3}, {%4,%5,%6,%7}, {%8,%9}, {%0,%1,%2,%3};" \
        : "+f"((d)[0]), "+f"((d)[1]), "+f"((d)[2]), "+f"((d)[3]) \
        : "r"((a)[0]), "r"((a)[1]), "r"((a)[2]), "r"((a)[3]), "r"(b0), "r"(b1))

static __device__ __forceinline__ float tanh_fast(float x) {
    float e = __expf(x + x);
    return 1.f - __fdividef(2.f, e + 1.f);
}

// ---------------------------------------------------------------------------
// Prep: We^T -> fp16 chunk images in LDSM-native block layout
// ---------------------------------------------------------------------------
__global__ void k_prep(const float* __restrict__ We) {
    int k = blockIdx.x, n = threadIdx.x;
    float v = We[k * 256 + n];
    int ch = k >> 5, kc = k & 31;
    int g = n >> 4, ks = kc >> 4, h16 = (kc >> 3) & 1;
    unsigned addr = (unsigned)((g * 2 + ks) * 512 + h16 * 256 + (n & 15) * 16 + (kc & 7) * 2);
    *(__half*)&g_Bt[ch][addr] = __float2half_rn(v);
}

// ---------------------------------------------------------------------------
// dpe[b,f] = dh[b,:]@Wd[:,f] + bd + be, paired with Wa
// ---------------------------------------------------------------------------
__global__ void k_decproj(const float* __restrict__ dh, const float* __restrict__ Wd,
                          const float* __restrict__ bd, const float* __restrict__ be,
                          const float* __restrict__ Wa) {
    int b = blockIdx.x, f = threadIdx.x;
    __shared__ float sdh[DEC_];
    for (int d = f; d < DEC_; d += ENC_) sdh[d] = dh[b * DEC_ + d];
    __syncthreads();
    float acc = bd[f] + be[f];
#pragma unroll 8
    for (int d = 0; d < DEC_; ++d) acc += sdh[d] * Wd[d * ENC_ + f];
    g_dw[b * ENC_ + f] = make_float2(acc, Wa[f]);
}

// ---------------------------------------------------------------------------
// k_scores: 64x256 tile, 256 thr, 2 CTAs/SM
//   A fp32 -> fp16 hi/lo split (exact), B fp16 single: 2 MMA terms per k16
// ---------------------------------------------------------------------------
static __device__ __forceinline__ void load_chunk(unsigned sb, const float* __restrict__ enc,
                                                  int row0, int c) {
    const int tid = threadIdx.x;
    const int buf = c & 1;
#pragma unroll
    for (int i = 0; i < 2; ++i) {                     // A stage: 512 float4 (single buf)
        int idx = tid + i * 256;
        int r = idx >> 3, seg = idx & 7;
        int unit = (((seg >> 1) ^ (r & 3)) << 1) + (seg & 1);
        cp16(sb + OSTG + (unsigned)r * 128u + (unsigned)unit * 16u,
             enc + (size_t)(row0 + r) * 256 + c * 32 + seg * 4);
    }
#pragma unroll
    for (int i = 0; i < 4; ++i) {                     // B image: 1024 x 16B contiguous
        int slot = tid + i * 256;
        cp16(sb + OBI(buf) + (unsigned)slot * 16u, &g_Bt[c][slot * 16]);
    }
    CP_COMMIT();
}

__global__ __launch_bounds__(256, 2)
void k_scores(const float* __restrict__ enc) {
    extern __shared__ __align__(16) unsigned char sm[];
    const unsigned sb = s2u(sm);
    const int tid = threadIdx.x, lane = tid & 31, w = tid >> 5;
    const int wr = w & 1, wc = w >> 1;                // 2 row-groups x 4 col-groups
    const int row0 = blockIdx.x * MT, b = row0 >> 12;

    load_chunk(sb, enc, row0, 0);
    ((float2*)(sm + ODW))[tid] = g_dw[b * 256 + tid];

    float acc[2][8][4];
#pragma unroll
    for (int mi = 0; mi < 2; ++mi)
#pragma unroll
        for (int ni = 0; ni < 8; ++ni)
#pragma unroll
            for (int q = 0; q < 4; ++q) acc[mi][ni][q] = 0.f;

    // per-lane ldmatrix offsets within a 512B block (LDSM-native layout)
    const unsigned a_lo = (unsigned)((lane & 15) * 16 + (lane >> 4) * 256);
    const unsigned b_lo = (unsigned)((lane & 7) * 16 + ((lane >> 4) & 1) * 128 +
                                     ((lane >> 3) & 1) * 256);

#pragma unroll 1
    for (int c = 0; c < 8; ++c) {
        const int buf = c & 1;
        CP_WAIT0();
        __syncthreads();
        // convert fp32 stage -> fp16 hi/lo images (8 floats / thread)
        {
            int r = tid >> 2, s = tid & 3;
            int pch = s ^ (r & 3);
            const float4* s4 = (const float4*)(sm + OSTG + (unsigned)r * 128u +
                                               (unsigned)pch * 32u);
            float4 v0 = s4[0], v1 = s4[1];
            float vf[8] = {v0.x, v0.y, v0.z, v0.w, v1.x, v1.y, v1.z, v1.w};
            unsigned hu[4], lu[4];
#pragma unroll
            for (int q = 0; q < 4; ++q) {
                __half h0 = __float2half_rn(vf[2 * q]);
                __half h1 = __float2half_rn(vf[2 * q + 1]);
                __half2 hp = __halves2half2(h0, h1);
                __half2 lp = __halves2half2(
                    __float2half_rn(vf[2 * q] - __half2float(h0)),
                    __float2half_rn(vf[2 * q + 1] - __half2float(h1)));
                hu[q] = *(unsigned*)&hp;
                lu[q] = *(unsigned*)&lp;
            }
            int g = r >> 4, ks = s >> 1, h16 = s & 1;
            unsigned doff = (unsigned)((g * 2 + ks) * 512 + h16 * 256 + (r & 15) * 16);
            asm volatile("st.shared.v4.b32 [%0], {%1,%2,%3,%4};"
                         :: "r"(sb + OAI(buf, 0) + doff),
                            "r"(hu[0]), "r"(hu[1]), "r"(hu[2]), "r"(hu[3]));
            asm volatile("st.shared.v4.b32 [%0], {%1,%2,%3,%4};"
                         :: "r"(sb + OAI(buf, 1) + doff),
                            "r"(lu[0]), "r"(lu[1]), "r"(lu[2]), "r"(lu[3]));
        }
        __syncthreads();
        if (c < 7) load_chunk(sb, enc, row0, c + 1);  // overlaps MMA below

        const unsigned ah_b = sb + OAI(buf, 0) + a_lo, al_b = sb + OAI(buf, 1) + a_lo;
        const unsigned bh_b = sb + OBI(buf) + b_lo;
#pragma unroll
        for (int ks = 0; ks < 2; ++ks) {
            unsigned af[2][4], bh[8][2];
#pragma unroll
            for (int mi = 0; mi < 2; ++mi)
                LDM4(af[mi], ah_b + (unsigned)(((wr * 2 + mi) * 2 + ks) * 512));
#pragma unroll
            for (int p = 0; p < 4; ++p) {
                const unsigned blk = (unsigned)(((wc * 4 + p) * 2 + ks) * 512);
                unsigned r4[4];
                LDM4(r4, bh_b + blk);
                bh[2 * p][0] = r4[0]; bh[2 * p][1] = r4[1];
                bh[2 * p + 1][0] = r4[2]; bh[2 * p + 1][1] = r4[3];
            }
#pragma unroll
            for (int mi = 0; mi < 2; ++mi)
#pragma unroll
                for (int ni = 0; ni < 8; ++ni)
                    MMAH(acc[mi][ni], af[mi], bh[ni][0], bh[ni][1]);
#pragma unroll
            for (int mi = 0; mi < 2; ++mi)            // reuse af regs for A_lo
                LDM4(af[mi], al_b + (unsigned)(((wr * 2 + mi) * 2 + ks) * 512));
#pragma unroll
            for (int mi = 0; mi < 2; ++mi)
#pragma unroll
                for (int ni = 0; ni < 8; ++ni)
                    MMAH(acc[mi][ni], af[mi], bh[ni][0], bh[ni][1]);
        }
    }

    // Epilogue: partial scores = sum_cols Wa * tanh(dpe + v); red reuses stage
    const float2* sdw = (const float2*)(sm + ODW);
    float* red = (float*)(sm + OSTG);                 // [64][5] padded
#pragma unroll
    for (int mi = 0; mi < 2; ++mi) {
        float p0 = 0.f, p1 = 0.f;
#pragma unroll
        for (int ni = 0; ni < 8; ++ni) {
            int cc = wc * 64 + ni * 8 + 2 * (lane & 3);
            float2 w0 = sdw[cc], w1 = sdw[cc + 1];
            p0 += w0.y * tanh_fast(acc[mi][ni][0] + w0.x) +
                  w1.y * tanh_fast(acc[mi][ni][1] + w1.x);
            p1 += w0.y * tanh_fast(acc[mi][ni][2] + w0.x) +
                  w1.y * tanh_fast(acc[mi][ni][3] + w1.x);
        }
        p0 += __shfl_xor_sync(~0u, p0, 1); p0 += __shfl_xor_sync(~0u, p0, 2);
        p1 += __shfl_xor_sync(~0u, p1, 1); p1 += __shfl_xor_sync(~0u, p1, 2);
        if ((lane & 3) == 0) {
            int r = wr * 32 + mi * 16 + (lane >> 2);
            red[r * 5 + wc] = p0;
            red[(r + 8) * 5 + wc] = p1;
        }
    }
    __syncthreads();
    if (tid < MT) {
        float s = red[tid * 5] + red[tid * 5 + 1] + red[tid * 5 + 2] + red[tid * 5 + 3];
        g_scores[row0 + tid] = s;
    }
}

// ---------------------------------------------------------------------------
// Masked softmax over S per batch
// ---------------------------------------------------------------------------
__global__ void k_softmax(const int* __restrict__ mask, float* __restrict__ attn) {
    const int b = blockIdx.x, t = threadIdx.x;
    const float* sc = g_scores + b * S_;
    const int* mk = mask + b * S_;
    float v[4], mx = -INFINITY;
#pragma unroll
    for (int i = 0; i < 4; ++i) {
        int s = t + i * 1024;
        float x = (mk[s] == 0) ? -1e10f : sc[s];
        v[i] = x; mx = fmaxf(mx, x);
    }
    __shared__ float rb[32];
    for (int o = 16; o; o >>= 1) mx = fmaxf(mx, __shfl_xor_sync(~0u, mx, o));
    if ((t & 31) == 0) rb[t >> 5] = mx;
    __syncthreads();
    if (t < 32) {
        float m2 = rb[t];
        for (int o = 16; o; o >>= 1) m2 = fmaxf(m2, __shfl_xor_sync(~0u, m2, o));
        rb[t] = m2;
    }
    __syncthreads();
    mx = rb[0];
    __syncthreads();
    float e[4], tot = 0.f;
#pragma unroll
    for (int i = 0; i < 4; ++i) { e[i] = expf(v[i] - mx); tot += e[i]; }
    for (int o = 16; o; o >>= 1) tot += __shfl_xor_sync(~0u, tot, o);
    if ((t & 31) == 0) rb[t >> 5] = tot;
    __syncthreads();
    if (t < 32) {
        float s2 = rb[t];
        for (int o = 16; o; o >>= 1) s2 += __shfl_xor_sync(~0u, s2, o);
        rb[t] = s2;
    }
    __syncthreads();
    const float inv = 1.f / rb[0];
#pragma unroll
    for (int i = 0; i < 4; ++i) attn[b * S_ + t + i * 1024] = e[i] * inv;
}

// ---------------------------------------------------------------------------
// Context: split S over 8 segments (512 CTAs) + reduce
// ---------------------------------------------------------------------------
__global__ void k_context(const float* __restrict__ enc, const float* __restrict__ attn) {
    const int seg = blockIdx.x & 7, b = blockIdx.x >> 3, t = threadIdx.x;
    const int c4 = t & 63, sg = t >> 6;
    const float4* e4 = (const float4*)enc + (size_t)b * S_ * 64;
    const float* at = attn + b * S_;
    float4 acc = make_float4(0.f, 0.f, 0.f, 0.f);
    const int s0 = seg * 512;
#pragma unroll 4
    for (int s = s0 + sg; s < s0 + 512; s += 4) {
        float a = at[s];
        float4 e = e4[(size_t)s * 64 + c4];
        acc.x += a * e.x; acc.y += a * e.y; acc.z += a * e.z; acc.w += a * e.w;
    }
    __shared__ float4 sr[4][64];
    sr[sg][c4] = acc;
    __syncthreads();
    if (t < 64) {
        float4 r = sr[0][t];
#pragma unroll
        for (int g = 1; g < 4; ++g) {
            float4 q = sr[g][t];
            r.x += q.x; r.y += q.y; r.z += q.z; r.w += q.w;
        }
        ((float4*)g_cpart)[(b * 8 + seg) * 64 + t] = r;
    }
}
__global__ void k_cred(float* __restrict__ ctx) {
    const int b = blockIdx.x, t = threadIdx.x;
    const float4* p = (const float4*)g_cpart;
    float4 r = make_float4(0.f, 0.f, 0.f, 0.f);
#pragma unroll
    for (int seg = 0; seg < 8; ++seg) {
        float4 q = p[(b * 8 + seg) * 64 + t];
        r.x += q.x; r.y += q.y; r.z += q.z; r.w += q.w;
    }
    ((float4*)ctx)[b * 64 + t] = r;
}

// ---------------------------------------------------------------------------
extern "C" void kernel_launch(void* const* d_in, const int* in_sizes, int n_in,
                              void* d_out, int out_size) {
    const float* dh   = (const float*)d_in[0];
    const float* enc  = (const float*)d_in[1];
    const int*   mask = (const int*)  d_in[2];
    const float* Wd   = (const float*)d_in[3];
    const float* bd   = (const float*)d_in[4];
    const float* We   = (const float*)d_in[5];
    const float* be   = (const float*)d_in[6];
    const float* Wa   = (const float*)d_in[7];
    // d_in[8] = ba: uniform shift on scores, cancels in softmax

    float* out  = (float*)d_out;
    float* ctx  = out;
    float* attn = out + B_ * ENC_;

    cudaFuncSetAttribute(k_scores, cudaFuncAttributeMaxDynamicSharedMemorySize, SMEM_BYTES);

    k_prep<<<256, 256>>>(We);
    k_decproj<<<B_, ENC_>>>(dh, Wd, bd, be, Wa);
    k_scores<<<(B_ * S_) / MT, 256, SMEM_BYTES>>>(enc);
    k_softmax<<<B_, 1024>>>(mask, attn);
    k_context<<<8 * B_, 256>>>(enc, attn);
    k_cred<<<B_, 64>>>(ctx);
}

// round 9
// speedup vs baseline: 1.6190x; 1.2257x over previous
#include <cuda_runtime.h>
#include <cuda_fp16.h>
#include <math.h>

#define B_   64
#define S_   4096
#define DEC_ 512
#define ENC_ 256
#define MT   64                                        // rows per k_scores tile

// ---------------- device scratch (allocation-free rule) ----------------
__device__ float2 g_dw[B_ * ENC_];                    // (dpe, Wa) per (b,f)
__device__ float  g_scores[B_ * S_];
__device__ float  g_cpart[8 * B_ * ENC_];
// We^T fp16 per K-chunk, LDSM-native block layout:
//   addr(n,kc) = (g*2+ks)*512 + h16*256 + (n&15)*16 + (kc&7)*2,
//   g=n>>4, ks=kc>>4, h16=(kc>>3)&1
__device__ __align__(16) unsigned char g_Bt[8][16384];

// ---------------- smem layout (bytes), per CTA = 51200 ----------------
#define OBI(buf)     ((unsigned)(buf) * 16384u)        // B fp16, 32K dbuf
#define OAI(buf)     (32768u + (unsigned)(buf) * 4096u) // A fp16, 8K dbuf
#define OSTG         40960u                            // fp32 stage [64][128B] (reused: red)
#define ODW          49152u                            // float2[256]
#define SMEM_BYTES   51200u

static __device__ __forceinline__ unsigned s2u(const void* p) {
    unsigned a;
    asm("{ .reg .u64 t; cvta.to.shared.u64 t, %1; cvt.u32.u64 %0, t; }" : "=r"(a) : "l"(p));
    return a;
}
static __device__ __forceinline__ void cp16(unsigned dst, const void* src) {
    asm volatile("cp.async.cg.shared.global [%0], [%1], 16;" :: "r"(dst), "l"(src));
}
#define CP_COMMIT() asm volatile("cp.async.commit_group;" ::: "memory")
#define CP_WAIT0()  asm volatile("cp.async.wait_group 0;" ::: "memory")

#define LDM4(r, addr) \
    asm volatile("ldmatrix.sync.aligned.m8n8.x4.shared.b16 {%0,%1,%2,%3}, [%4];" \
        : "=r"((r)[0]), "=r"((r)[1]), "=r"((r)[2]), "=r"((r)[3]) : "r"(addr))

#define MMAH(d, a, b0, b1) \
    asm volatile("mma.sync.aligned.m16n8k16.row.col.f32.f16.f16.f32 " \
        "{%0,%1,%2,%3}, {%4,%5,%6,%7}, {%8,%9}, {%0,%1,%2,%3};" \
        : "+f"((d)[0]), "+f"((d)[1]), "+f"((d)[2]), "+f"((d)[3]) \
        : "r"((a)[0]), "r"((a)[1]), "r"((a)[2]), "r"((a)[3]), "r"(b0), "r"(b1))

static __device__ __forceinline__ float tanh_fast(float x) {
    float e = __expf(x + x);
    return 1.f - __fdividef(2.f, e + 1.f);
}

// ---------------------------------------------------------------------------
// Prep: We^T -> fp16 chunk images in LDSM-native block layout
// ---------------------------------------------------------------------------
__global__ void k_prep(const float* __restrict__ We) {
    int k = blockIdx.x, n = threadIdx.x;
    float v = We[k * 256 + n];
    int ch = k >> 5, kc = k & 31;
    int g = n >> 4, ks = kc >> 4, h16 = (kc >> 3) & 1;
    unsigned addr = (unsigned)((g * 2 + ks) * 512 + h16 * 256 + (n & 15) * 16 + (kc & 7) * 2);
    *(__half*)&g_Bt[ch][addr] = __float2half_rn(v);
}

// ---------------------------------------------------------------------------
// dpe[b,f] = dh[b,:]@Wd[:,f] + bd + be, paired with Wa
// ---------------------------------------------------------------------------
__global__ void k_decproj(const float* __restrict__ dh, const float* __restrict__ Wd,
                          const float* __restrict__ bd, const float* __restrict__ be,
                          const float* __restrict__ Wa) {
    int b = blockIdx.x, f = threadIdx.x;
    __shared__ float sdh[DEC_];
    for (int d = f; d < DEC_; d += ENC_) sdh[d] = dh[b * DEC_ + d];
    __syncthreads();
    float acc = bd[f] + be[f];
#pragma unroll 8
    for (int d = 0; d < DEC_; ++d) acc += sdh[d] * Wd[d * ENC_ + f];
    g_dw[b * ENC_ + f] = make_float2(acc, Wa[f]);
}

// ---------------------------------------------------------------------------
// k_scores: 64x256 tile, 256 thr, 2 CTAs/SM
//   A fp16 (single), B fp16 (single): 1 MMA term per k16 step
// ---------------------------------------------------------------------------
static __device__ __forceinline__ void load_chunk(unsigned sb, const float* __restrict__ enc,
                                                  int row0, int c) {
    const int tid = threadIdx.x;
    const int buf = c & 1;
#pragma unroll
    for (int i = 0; i < 2; ++i) {                     // A stage: 512 float4 (single buf)
        int idx = tid + i * 256;
        int r = idx >> 3, seg = idx & 7;
        int unit = (((seg >> 1) ^ (r & 3)) << 1) + (seg & 1);
        cp16(sb + OSTG + (unsigned)r * 128u + (unsigned)unit * 16u,
             enc + (size_t)(row0 + r) * 256 + c * 32 + seg * 4);
    }
#pragma unroll
    for (int i = 0; i < 4; ++i) {                     // B image: 1024 x 16B contiguous
        int slot = tid + i * 256;
        cp16(sb + OBI(buf) + (unsigned)slot * 16u, &g_Bt[c][slot * 16]);
    }
    CP_COMMIT();
}

__global__ __launch_bounds__(256, 2)
void k_scores(const float* __restrict__ enc) {
    extern __shared__ __align__(16) unsigned char sm[];
    const unsigned sb = s2u(sm);
    const int tid = threadIdx.x, lane = tid & 31, w = tid >> 5;
    const int wr = w & 1, wc = w >> 1;                // 2 row-groups x 4 col-groups
    const int row0 = blockIdx.x * MT, b = row0 >> 12;

    load_chunk(sb, enc, row0, 0);
    ((float2*)(sm + ODW))[tid] = g_dw[b * 256 + tid];

    float acc[2][8][4];
#pragma unroll
    for (int mi = 0; mi < 2; ++mi)
#pragma unroll
        for (int ni = 0; ni < 8; ++ni)
#pragma unroll
            for (int q = 0; q < 4; ++q) acc[mi][ni][q] = 0.f;

    // per-lane ldmatrix offsets within a 512B block (LDSM-native layout)
    const unsigned a_lo = (unsigned)((lane & 15) * 16 + (lane >> 4) * 256);
    const unsigned b_lo = (unsigned)((lane & 7) * 16 + ((lane >> 4) & 1) * 128 +
                                     ((lane >> 3) & 1) * 256);

#pragma unroll 1
    for (int c = 0; c < 8; ++c) {
        const int buf = c & 1;
        CP_WAIT0();
        __syncthreads();
        // convert fp32 stage -> fp16 image (8 floats / thread)
        {
            int r = tid >> 2, s = tid & 3;
            int pch = s ^ (r & 3);
            const float4* s4 = (const float4*)(sm + OSTG + (unsigned)r * 128u +
                                               (unsigned)pch * 32u);
            float4 v0 = s4[0], v1 = s4[1];
            float vf[8] = {v0.x, v0.y, v0.z, v0.w, v1.x, v1.y, v1.z, v1.w};
            unsigned hu[4];
#pragma unroll
            for (int q = 0; q < 4; ++q) {
                __half2 hp = __halves2half2(__float2half_rn(vf[2 * q]),
                                            __float2half_rn(vf[2 * q + 1]));
                hu[q] = *(unsigned*)&hp;
            }
            int g = r >> 4, ks = s >> 1, h16 = s & 1;
            unsigned doff = (unsigned)((g * 2 + ks) * 512 + h16 * 256 + (r & 15) * 16);
            asm volatile("st.shared.v4.b32 [%0], {%1,%2,%3,%4};"
                         :: "r"(sb + OAI(buf) + doff),
                            "r"(hu[0]), "r"(hu[1]), "r"(hu[2]), "r"(hu[3]));
        }
        __syncthreads();
        if (c < 7) load_chunk(sb, enc, row0, c + 1);  // overlaps MMA below

        const unsigned ah_b = sb + OAI(buf) + a_lo;
        const unsigned bh_b = sb + OBI(buf) + b_lo;
#pragma unroll
        for (int ks = 0; ks < 2; ++ks) {
            unsigned af[2][4], bh[8][2];
#pragma unroll
            for (int mi = 0; mi < 2; ++mi)
                LDM4(af[mi], ah_b + (unsigned)(((wr * 2 + mi) * 2 + ks) * 512));
#pragma unroll
            for (int p = 0; p < 4; ++p) {
                const unsigned blk = (unsigned)(((wc * 4 + p) * 2 + ks) * 512);
                unsigned r4[4];
                LDM4(r4, bh_b + blk);
                bh[2 * p][0] = r4[0]; bh[2 * p][1] = r4[1];
                bh[2 * p + 1][0] = r4[2]; bh[2 * p + 1][1] = r4[3];
            }
#pragma unroll
            for (int mi = 0; mi < 2; ++mi)
#pragma unroll
                for (int ni = 0; ni < 8; ++ni)
                    MMAH(acc[mi][ni], af[mi], bh[ni][0], bh[ni][1]);
        }
    }

    // Epilogue: partial scores = sum_cols Wa * tanh(dpe + v); red reuses stage
    const float2* sdw = (const float2*)(sm + ODW);
    float* red = (float*)(sm + OSTG);                 // [64][5] padded
#pragma unroll
    for (int mi = 0; mi < 2; ++mi) {
        float p0 = 0.f, p1 = 0.f;
#pragma unroll
        for (int ni = 0; ni < 8; ++ni) {
            int cc = wc * 64 + ni * 8 + 2 * (lane & 3);
            float2 w0 = sdw[cc], w1 = sdw[cc + 1];
            p0 += w0.y * tanh_fast(acc[mi][ni][0] + w0.x) +
                  w1.y * tanh_fast(acc[mi][ni][1] + w1.x);
            p1 += w0.y * tanh_fast(acc[mi][ni][2] + w0.x) +
                  w1.y * tanh_fast(acc[mi][ni][3] + w1.x);
        }
        p0 += __shfl_xor_sync(~0u, p0, 1); p0 += __shfl_xor_sync(~0u, p0, 2);
        p1 += __shfl_xor_sync(~0u, p1, 1); p1 += __shfl_xor_sync(~0u, p1, 2);
        if ((lane & 3) == 0) {
            int r = wr * 32 + mi * 16 + (lane >> 2);
            red[r * 5 + wc] = p0;
            red[(r + 8) * 5 + wc] = p1;
        }
    }
    __syncthreads();
    if (tid < MT) {
        float s = red[tid * 5] + red[tid * 5 + 1] + red[tid * 5 + 2] + red[tid * 5 + 3];
        g_scores[row0 + tid] = s;
    }
}

// ---------------------------------------------------------------------------
// Masked softmax over S per batch
// ---------------------------------------------------------------------------
__global__ void k_softmax(const int* __restrict__ mask, float* __restrict__ attn) {
    const int b = blockIdx.x, t = threadIdx.x;
    const float* sc = g_scores + b * S_;
    const int* mk = mask + b * S_;
    float v[4], mx = -INFINITY;
#pragma unroll
    for (int i = 0; i < 4; ++i) {
        int s = t + i * 1024;
        float x = (mk[s] == 0) ? -1e10f : sc[s];
        v[i] = x; mx = fmaxf(mx, x);
    }
    __shared__ float rb[32];
    for (int o = 16; o; o >>= 1) mx = fmaxf(mx, __shfl_xor_sync(~0u, mx, o));
    if ((t & 31) == 0) rb[t >> 5] = mx;
    __syncthreads();
    if (t < 32) {
        float m2 = rb[t];
        for (int o = 16; o; o >>= 1) m2 = fmaxf(m2, __shfl_xor_sync(~0u, m2, o));
        rb[t] = m2;
    }
    __syncthreads();
    mx = rb[0];
    __syncthreads();
    float e[4], tot = 0.f;
#pragma unroll
    for (int i = 0; i < 4; ++i) { e[i] = expf(v[i] - mx); tot += e[i]; }
    for (int o = 16; o; o >>= 1) tot += __shfl_xor_sync(~0u, tot, o);
    if ((t & 31) == 0) rb[t >> 5] = tot;
    __syncthreads();
    if (t < 32) {
        float s2 = rb[t];
        for (int o = 16; o; o >>= 1) s2 += __shfl_xor_sync(~0u, s2, o);
        rb[t] = s2;
    }
    __syncthreads();
    const float inv = 1.f / rb[0];
#pragma unroll
    for (int i = 0; i < 4; ++i) attn[b * S_ + t + i * 1024] = e[i] * inv;
}

// ---------------------------------------------------------------------------
// Context: split S over 8 segments (512 CTAs) + reduce
// ---------------------------------------------------------------------------
__global__ void k_context(const float* __restrict__ enc, const float* __restrict__ attn) {
    const int seg = blockIdx.x & 7, b = blockIdx.x >> 3, t = threadIdx.x;
    const int c4 = t & 63, sg = t >> 6;
    const float4* e4 = (const float4*)enc + (size_t)b * S_ * 64;
    const float* at = attn + b * S_;
    float4 acc = make_float4(0.f, 0.f, 0.f, 0.f);
    const int s0 = seg * 512;
#pragma unroll 4
    for (int s = s0 + sg; s < s0 + 512; s += 4) {
        float a = at[s];
        float4 e = e4[(size_t)s * 64 + c4];
        acc.x += a * e.x; acc.y += a * e.y; acc.z += a * e.z; acc.w += a * e.w;
    }
    __shared__ float4 sr[4][64];
    sr[sg][c4] = acc;
    __syncthreads();
    if (t < 64) {
        float4 r = sr[0][t];
#pragma unroll
        for (int g = 1; g < 4; ++g) {
            float4 q = sr[g][t];
            r.x += q.x; r.y += q.y; r.z += q.z; r.w += q.w;
        }
        ((float4*)g_cpart)[(b * 8 + seg) * 64 + t] = r;
    }
}
__global__ void k_cred(float* __restrict__ ctx) {
    const int b = blockIdx.x, t = threadIdx.x;
    const float4* p = (const float4*)g_cpart;
    float4 r = make_float4(0.f, 0.f, 0.f, 0.f);
#pragma unroll
    for (int seg = 0; seg < 8; ++seg) {
        float4 q = p[(b * 8 + seg) * 64 + t];
        r.x += q.x; r.y += q.y; r.z += q.z; r.w += q.w;
    }
    ((float4*)ctx)[b * 64 + t] = r;
}

// ---------------------------------------------------------------------------
extern "C" void kernel_launch(void* const* d_in, const int* in_sizes, int n_in,
                              void* d_out, int out_size) {
    const float* dh   = (const float*)d_in[0];
    const float* enc  = (const float*)d_in[1];
    const int*   mask = (const int*)  d_in[2];
    const float* Wd   = (const float*)d_in[3];
    const float* bd   = (const float*)d_in[4];
    const float* We   = (const float*)d_in[5];
    const float* be   = (const float*)d_in[6];
    const float* Wa   = (const float*)d_in[7];
    // d_in[8] = ba: uniform shift on scores, cancels in softmax

    float* out  = (float*)d_out;
    float* ctx  = out;
    float* attn = out + B_ * ENC_;

    cudaFuncSetAttribute(k_scores, cudaFuncAttributeMaxDynamicSharedMemorySize, SMEM_BYTES);

    k_prep<<<256, 256>>>(We);
    k_decproj<<<B_, ENC_>>>(dh, Wd, bd, be, Wa);
    k_scores<<<(B_ * S_) / MT, 256, SMEM_BYTES>>>(enc);
    k_softmax<<<B_, 1024>>>(mask, attn);
    k_context<<<8 * B_, 256>>>(enc, attn);
    k_cred<<<B_, 64>>>(ctx);
}

// round 10
// speedup vs baseline: 1.7791x; 1.0989x over previous
#include <cuda_runtime.h>
#include <cuda_fp16.h>
#include <math.h>

#define B_   64
#define S_   4096
#define DEC_ 512
#define ENC_ 256
#define MT   64                                        // rows per k_scores tile

// ---------------- device scratch (allocation-free rule) ----------------
__device__ float2 g_dw[B_ * ENC_];                    // (dpe, Wa) per (b,f)
__device__ float  g_scores[B_ * S_];
__device__ float  g_cpart[8 * B_ * ENC_];
// We^T fp16 per K-chunk, LDSM-native block layout:
//   addr(n,kc) = (g*2+ks)*512 + h16*256 + (n&15)*16 + (kc&7)*2,
//   g=n>>4, ks=kc>>4, h16=(kc>>3)&1
__device__ __align__(16) unsigned char g_Bt[8][16384];

// ---------------- smem layout (bytes), per CTA = 43008 ----------------
#define OBI(buf)     ((unsigned)(buf) * 16384u)        // B fp16, 32K dbuf (buf0 reused: red)
#define OAI(buf)     (32768u + (unsigned)(buf) * 4096u) // A fp16 img, 8K dbuf
#define ODW          40960u                            // float2[256]
#define SMEM_BYTES   43008u

static __device__ __forceinline__ unsigned s2u(const void* p) {
    unsigned a;
    asm("{ .reg .u64 t; cvta.to.shared.u64 t, %1; cvt.u32.u64 %0, t; }" : "=r"(a) : "l"(p));
    return a;
}
static __device__ __forceinline__ void cp16(unsigned dst, const void* src) {
    asm volatile("cp.async.cg.shared.global [%0], [%1], 16;" :: "r"(dst), "l"(src));
}
#define CP_COMMIT() asm volatile("cp.async.commit_group;" ::: "memory")
#define CP_WAIT0()  asm volatile("cp.async.wait_group 0;" ::: "memory")

#define LDM4(r, addr) \
    asm volatile("ldmatrix.sync.aligned.m8n8.x4.shared.b16 {%0,%1,%2,%3}, [%4];" \
        : "=r"((r)[0]), "=r"((r)[1]), "=r"((r)[2]), "=r"((r)[3]) : "r"(addr))

#define MMAH(d, a, b0, b1) \
    asm volatile("mma.sync.aligned.m16n8k16.row.col.f32.f16.f16.f32 " \
        "{%0,%1,%2,%3}, {%4,%5,%6,%7}, {%8,%9}, {%0,%1,%2,%3};" \
        : "+f"((d)[0]), "+f"((d)[1]), "+f"((d)[2]), "+f"((d)[3]) \
        : "r"((a)[0]), "r"((a)[1]), "r"((a)[2]), "r"((a)[3]), "r"(b0), "r"(b1))

static __device__ __forceinline__ float tanha(float x) {
    float y;
    asm("tanh.approx.f32 %0, %1;" : "=f"(y) : "f"(x));
    return y;
}

// ---------------------------------------------------------------------------
// Prep: We^T -> fp16 chunk images in LDSM-native block layout
// ---------------------------------------------------------------------------
__global__ void k_prep(const float* __restrict__ We) {
    int k = blockIdx.x, n = threadIdx.x;
    float v = We[k * 256 + n];
    int ch = k >> 5, kc = k & 31;
    int g = n >> 4, ks = kc >> 4, h16 = (kc >> 3) & 1;
    unsigned addr = (unsigned)((g * 2 + ks) * 512 + h16 * 256 + (n & 15) * 16 + (kc & 7) * 2);
    *(__half*)&g_Bt[ch][addr] = __float2half_rn(v);
}

// ---------------------------------------------------------------------------
// dpe[b,f] = dh[b,:]@Wd[:,f] + bd + be, paired with Wa
// ---------------------------------------------------------------------------
__global__ void k_decproj(const float* __restrict__ dh, const float* __restrict__ Wd,
                          const float* __restrict__ bd, const float* __restrict__ be,
                          const float* __restrict__ Wa) {
    int b = blockIdx.x, f = threadIdx.x;
    __shared__ float sdh[DEC_];
    for (int d = f; d < DEC_; d += ENC_) sdh[d] = dh[b * DEC_ + d];
    __syncthreads();
    float acc = bd[f] + be[f];
#pragma unroll 8
    for (int d = 0; d < DEC_; ++d) acc += sdh[d] * Wd[d * ENC_ + f];
    g_dw[b * ENC_ + f] = make_float2(acc, Wa[f]);
}

// ---------------------------------------------------------------------------
// k_scores: 64x256 tile, 256 thr, 2 CTAs/SM, fp16 x fp16 single-term HMMA
//   A: LDG fp32 -> regs -> fp16 STS (no smem stage); B: cp.async images
// ---------------------------------------------------------------------------
static __device__ __forceinline__ void loadB(unsigned sb, int c, int tid) {
#pragma unroll
    for (int i = 0; i < 4; ++i) {                     // 1024 x 16B contiguous
        int slot = tid + i * 256;
        cp16(sb + OBI(c & 1) + (unsigned)slot * 16u, &g_Bt[c][slot * 16]);
    }
    CP_COMMIT();
}
static __device__ __forceinline__ void cvtstore(unsigned dst, float4 v0, float4 v1) {
    float vf[8] = {v0.x, v0.y, v0.z, v0.w, v1.x, v1.y, v1.z, v1.w};
    unsigned hu[4];
#pragma unroll
    for (int q = 0; q < 4; ++q) {
        __half2 hp = __halves2half2(__float2half_rn(vf[2 * q]),
                                    __float2half_rn(vf[2 * q + 1]));
        hu[q] = *(unsigned*)&hp;
    }
    asm volatile("st.shared.v4.b32 [%0], {%1,%2,%3,%4};"
                 :: "r"(dst), "r"(hu[0]), "r"(hu[1]), "r"(hu[2]), "r"(hu[3]));
}

__global__ __launch_bounds__(256, 2)
void k_scores(const float* __restrict__ enc) {
    extern __shared__ __align__(16) unsigned char sm[];
    const unsigned sb = s2u(sm);
    const int tid = threadIdx.x, lane = tid & 31, w = tid >> 5;
    const int wr = w & 1, wc = w >> 1;                // 2 row-groups x 4 col-groups
    const int row0 = blockIdx.x * MT, b = row0 >> 12;

    // this thread's A slice: row r, k-bytes [s*8, s*8+8) of each 32-wide chunk
    const int r_ = tid >> 2, s_ = tid & 3;
    const float4* ap = (const float4*)(enc + (size_t)(row0 + r_) * 256 + s_ * 8);
    const unsigned adst = (unsigned)(((r_ >> 4) * 2 + (s_ >> 1)) * 512 +
                                     (s_ & 1) * 256 + (r_ & 15) * 16);

    loadB(sb, 0, tid);                                // B(0) in flight ASAP
    ((float2*)(sm + ODW))[tid] = g_dw[b * 256 + tid];

    float4 r0 = ap[0], r1 = ap[1];                    // A chunk 0
    cvtstore(sb + OAI(0) + adst, r0, r1);
    CP_WAIT0();                                       // B(0) (own-thread; cross via sync)

    float acc[2][8][4];
#pragma unroll
    for (int mi = 0; mi < 2; ++mi)
#pragma unroll
        for (int ni = 0; ni < 8; ++ni)
#pragma unroll
            for (int q = 0; q < 4; ++q) acc[mi][ni][q] = 0.f;

    // per-lane ldmatrix offsets within a 512B block (LDSM-native layout)
    const unsigned a_lo = (unsigned)((lane & 15) * 16 + (lane >> 4) * 256);
    const unsigned b_lo = (unsigned)((lane & 7) * 16 + ((lane >> 4) & 1) * 128 +
                                     ((lane >> 3) & 1) * 256);

#pragma unroll 1
    for (int c = 0; c < 8; ++c) {
        const int buf = c & 1;
        __syncthreads();                              // A-img[c], B[c] visible to all
        if (c < 7) {
            loadB(sb, c + 1, tid);                    // B(c+1) overlaps MMA+cvt
            r0 = ap[(c + 1) * 8];                     // A(c+1) LDG in flight
            r1 = ap[(c + 1) * 8 + 1];
        }

        const unsigned ah_b = sb + OAI(buf) + a_lo;
        const unsigned bh_b = sb + OBI(buf) + b_lo;
#pragma unroll
        for (int ks = 0; ks < 2; ++ks) {
            unsigned af[2][4], bh[8][2];
#pragma unroll
            for (int mi = 0; mi < 2; ++mi)
                LDM4(af[mi], ah_b + (unsigned)(((wr * 2 + mi) * 2 + ks) * 512));
#pragma unroll
            for (int p = 0; p < 4; ++p) {
                const unsigned blk = (unsigned)(((wc * 4 + p) * 2 + ks) * 512);
                unsigned r4[4];
                LDM4(r4, bh_b + blk);
                bh[2 * p][0] = r4[0]; bh[2 * p][1] = r4[1];
                bh[2 * p + 1][0] = r4[2]; bh[2 * p + 1][1] = r4[3];
            }
#pragma unroll
            for (int mi = 0; mi < 2; ++mi)
#pragma unroll
                for (int ni = 0; ni < 8; ++ni)
                    MMAH(acc[mi][ni], af[mi], bh[ni][0], bh[ni][1]);
        }
        if (c < 7) {
            cvtstore(sb + OAI(buf ^ 1) + adst, r0, r1);  // overlaps other warps' MMA
            CP_WAIT0();                                  // B(c+1) landed (own thread)
        }
    }

    // Epilogue: partial scores = sum_cols Wa * tanh(dpe + v); red reuses B buf 0
    const float2* sdw = (const float2*)(sm + ODW);
    float* red = (float*)(sm + OBI(0));               // [64][5] padded
#pragma unroll
    for (int mi = 0; mi < 2; ++mi) {
        float p0 = 0.f, p1 = 0.f;
#pragma unroll
        for (int ni = 0; ni < 8; ++ni) {
            int cc = wc * 64 + ni * 8 + 2 * (lane & 3);
            float2 w0 = sdw[cc], w1 = sdw[cc + 1];
            p0 += w0.y * tanha(acc[mi][ni][0] + w0.x) +
                  w1.y * tanha(acc[mi][ni][1] + w1.x);
            p1 += w0.y * tanha(acc[mi][ni][2] + w0.x) +
                  w1.y * tanha(acc[mi][ni][3] + w1.x);
        }
        p0 += __shfl_xor_sync(~0u, p0, 1); p0 += __shfl_xor_sync(~0u, p0, 2);
        p1 += __shfl_xor_sync(~0u, p1, 1); p1 += __shfl_xor_sync(~0u, p1, 2);
        if ((lane & 3) == 0) {
            int r = wr * 32 + mi * 16 + (lane >> 2);
            red[r * 5 + wc] = p0;
            red[(r + 8) * 5 + wc] = p1;
        }
    }
    __syncthreads();
    if (tid < MT) {
        float s = red[tid * 5] + red[tid * 5 + 1] + red[tid * 5 + 2] + red[tid * 5 + 3];
        g_scores[row0 + tid] = s;
    }
}

// ---------------------------------------------------------------------------
// Masked softmax over S per batch
// ---------------------------------------------------------------------------
__global__ void k_softmax(const int* __restrict__ mask, float* __restrict__ attn) {
    const int b = blockIdx.x, t = threadIdx.x;
    const float* sc = g_scores + b * S_;
    const int* mk = mask + b * S_;
    float v[4], mx = -INFINITY;
#pragma unroll
    for (int i = 0; i < 4; ++i) {
        int s = t + i * 1024;
        float x = (mk[s] == 0) ? -1e10f : sc[s];
        v[i] = x; mx = fmaxf(mx, x);
    }
    __shared__ float rb[32];
    for (int o = 16; o; o >>= 1) mx = fmaxf(mx, __shfl_xor_sync(~0u, mx, o));
    if ((t & 31) == 0) rb[t >> 5] = mx;
    __syncthreads();
    if (t < 32) {
        float m2 = rb[t];
        for (int o = 16; o; o >>= 1) m2 = fmaxf(m2, __shfl_xor_sync(~0u, m2, o));
        rb[t] = m2;
    }
    __syncthreads();
    mx = rb[0];
    __syncthreads();
    float e[4], tot = 0.f;
#pragma unroll
    for (int i = 0; i < 4; ++i) { e[i] = expf(v[i] - mx); tot += e[i]; }
    for (int o = 16; o; o >>= 1) tot += __shfl_xor_sync(~0u, tot, o);
    if ((t & 31) == 0) rb[t >> 5] = tot;
    __syncthreads();
    if (t < 32) {
        float s2 = rb[t];
        for (int o = 16; o; o >>= 1) s2 += __shfl_xor_sync(~0u, s2, o);
        rb[t] = s2;
    }
    __syncthreads();
    const float inv = 1.f / rb[0];
#pragma unroll
    for (int i = 0; i < 4; ++i) attn[b * S_ + t + i * 1024] = e[i] * inv;
}

// ---------------------------------------------------------------------------
// Context: split S over 8 segments (512 CTAs) + reduce
// ---------------------------------------------------------------------------
__global__ void k_context(const float* __restrict__ enc, const float* __restrict__ attn) {
    const int seg = blockIdx.x & 7, b = blockIdx.x >> 3, t = threadIdx.x;
    const int c4 = t & 63, sg = t >> 6;
    const float4* e4 = (const float4*)enc + (size_t)b * S_ * 64;
    const float* at = attn + b * S_;
    float4 acc = make_float4(0.f, 0.f, 0.f, 0.f);
    const int s0 = seg * 512;
#pragma unroll 4
    for (int s = s0 + sg; s < s0 + 512; s += 4) {
        float a = at[s];
        float4 e = e4[(size_t)s * 64 + c4];
        acc.x += a * e.x; acc.y += a * e.y; acc.z += a * e.z; acc.w += a * e.w;
    }
    __shared__ float4 sr[4][64];
    sr[sg][c4] = acc;
    __syncthreads();
    if (t < 64) {
        float4 r = sr[0][t];
#pragma unroll
        for (int g = 1; g < 4; ++g) {
            float4 q = sr[g][t];
            r.x += q.x; r.y += q.y; r.z += q.z; r.w += q.w;
        }
        ((float4*)g_cpart)[(b * 8 + seg) * 64 + t] = r;
    }
}
__global__ void k_cred(float* __restrict__ ctx) {
    const int b = blockIdx.x, t = threadIdx.x;
    const float4* p = (const float4*)g_cpart;
    float4 r = make_float4(0.f, 0.f, 0.f, 0.f);
#pragma unroll
    for (int seg = 0; seg < 8; ++seg) {
        float4 q = p[(b * 8 + seg) * 64 + t];
        r.x += q.x; r.y += q.y; r.z += q.z; r.w += q.w;
    }
    ((float4*)ctx)[b * 64 + t] = r;
}

// ---------------------------------------------------------------------------
extern "C" void kernel_launch(void* const* d_in, const int* in_sizes, int n_in,
                              void* d_out, int out_size) {
    const float* dh   = (const float*)d_in[0];
    const float* enc  = (const float*)d_in[1];
    const int*   mask = (const int*)  d_in[2];
    const float* Wd   = (const float*)d_in[3];
    const float* bd   = (const float*)d_in[4];
    const float* We   = (const float*)d_in[5];
    const float* be   = (const float*)d_in[6];
    const float* Wa   = (const float*)d_in[7];
    // d_in[8] = ba: uniform shift on scores, cancels in softmax

    float* out  = (float*)d_out;
    float* ctx  = out;
    float* attn = out + B_ * ENC_;

    cudaFuncSetAttribute(k_scores, cudaFuncAttributeMaxDynamicSharedMemorySize, SMEM_BYTES);

    k_prep<<<256, 256>>>(We);
    k_decproj<<<B_, ENC_>>>(dh, Wd, bd, be, Wa);
    k_scores<<<(B_ * S_) / MT, 256, SMEM_BYTES>>>(enc);
    k_softmax<<<B_, 1024>>>(mask, attn);
    k_context<<<8 * B_, 256>>>(enc, attn);
    k_cred<<<B_, 64>>>(ctx);
}

// round 11
// speedup vs baseline: 2.3606x; 1.3268x over previous
#include <cuda_runtime.h>
#include <cuda_fp16.h>
#include <math.h>

#define B_   64
#define S_   4096
#define DEC_ 512
#define ENC_ 256
#define MT   64                                        // rows per k_scores tile

// ---------------- device scratch (allocation-free rule) ----------------
__device__ float2 g_dw[B_ * ENC_];                    // (dpe, Wa) per (b,f)
__device__ float  g_scores[B_ * S_];                  // compacted scores
__device__ float  g_attnc[B_ * S_];                   // compacted attn
__device__ int    g_idx[B_ * S_];                     // unmasked index lists
__device__ int    g_cnt[B_];                          // unmasked counts
__device__ float  g_cpart[8 * B_ * ENC_];
// We^T fp16 per K-chunk, LDSM-native block layout:
//   addr(n,kc) = (g*2+ks)*512 + h16*256 + (n&15)*16 + (kc&7)*2
__device__ __align__(16) unsigned char g_Bt[8][16384];

// ---------------- smem layout (bytes), per CTA = 43008 ----------------
#define OBI(buf)     ((unsigned)(buf) * 16384u)        // B fp16, 32K dbuf (buf0 reused: red)
#define OAI(buf)     (32768u + (unsigned)(buf) * 4096u) // A fp16 img, 8K dbuf
#define ODW          40960u                            // float2[256]
#define SMEM_BYTES   43008u

static __device__ __forceinline__ unsigned s2u(const void* p) {
    unsigned a;
    asm("{ .reg .u64 t; cvta.to.shared.u64 t, %1; cvt.u32.u64 %0, t; }" : "=r"(a) : "l"(p));
    return a;
}
static __device__ __forceinline__ void cp16(unsigned dst, const void* src) {
    asm volatile("cp.async.cg.shared.global [%0], [%1], 16;" :: "r"(dst), "l"(src));
}
#define CP_COMMIT() asm volatile("cp.async.commit_group;" ::: "memory")
#define CP_WAIT0()  asm volatile("cp.async.wait_group 0;" ::: "memory")

#define LDM4(r, addr) \
    asm volatile("ldmatrix.sync.aligned.m8n8.x4.shared.b16 {%0,%1,%2,%3}, [%4];" \
        : "=r"((r)[0]), "=r"((r)[1]), "=r"((r)[2]), "=r"((r)[3]) : "r"(addr))

#define MMAH(d, a, b0, b1) \
    asm volatile("mma.sync.aligned.m16n8k16.row.col.f32.f16.f16.f32 " \
        "{%0,%1,%2,%3}, {%4,%5,%6,%7}, {%8,%9}, {%0,%1,%2,%3};" \
        : "+f"((d)[0]), "+f"((d)[1]), "+f"((d)[2]), "+f"((d)[3]) \
        : "r"((a)[0]), "r"((a)[1]), "r"((a)[2]), "r"((a)[3]), "r"(b0), "r"(b1))

static __device__ __forceinline__ float tanha(float x) {
    float y;
    asm("tanh.approx.f32 %0, %1;" : "=f"(y) : "f"(x));
    return y;
}

// ---------------------------------------------------------------------------
// Prep: We^T -> fp16 chunk images in LDSM-native block layout
// ---------------------------------------------------------------------------
__global__ void k_prep(const float* __restrict__ We) {
    int k = blockIdx.x, n = threadIdx.x;
    float v = We[k * 256 + n];
    int ch = k >> 5, kc = k & 31;
    int g = n >> 4, ks = kc >> 4, h16 = (kc >> 3) & 1;
    unsigned addr = (unsigned)((g * 2 + ks) * 512 + h16 * 256 + (n & 15) * 16 + (kc & 7) * 2);
    *(__half*)&g_Bt[ch][addr] = __float2half_rn(v);
}

// ---------------------------------------------------------------------------
// Compact: per batch, list of unmasked indices; zero attn at masked positions
// ---------------------------------------------------------------------------
__global__ void k_compact(const int* __restrict__ mask, float* __restrict__ attn) {
    const int b = blockIdx.x, t = threadIdx.x;        // 1024 threads
    const int4 m = ((const int4*)(mask + b * S_))[t];
    int c0 = m.x != 0, c1 = m.y != 0, c2 = m.z != 0, c3 = m.w != 0;
    const int ls = c0 + c1 + c2 + c3;
    const int lane = t & 31, wid = t >> 5;
    int ws = ls;
#pragma unroll
    for (int o = 1; o < 32; o <<= 1) {
        int v = __shfl_up_sync(~0u, ws, o);
        if (lane >= o) ws += v;
    }
    __shared__ int wsum[32];
    if (lane == 31) wsum[wid] = ws;
    __syncthreads();
    if (t < 32) {
        int v = wsum[t];
#pragma unroll
        for (int o = 1; o < 32; o <<= 1) {
            int u = __shfl_up_sync(~0u, v, o);
            if (t >= o) v += u;
        }
        wsum[t] = v;
    }
    __syncthreads();
    int p = (wid ? wsum[wid - 1] : 0) + (ws - ls);    // exclusive prefix
    const int s = t * 4;
    int* gi = g_idx + b * S_;
    float* at = attn + b * S_;
    if (c0) gi[p++] = s;     else at[s]     = 0.f;
    if (c1) gi[p++] = s + 1; else at[s + 1] = 0.f;
    if (c2) gi[p++] = s + 2; else at[s + 2] = 0.f;
    if (c3) gi[p++] = s + 3; else at[s + 3] = 0.f;
    if (t == 1023) g_cnt[b] = p;
}

// ---------------------------------------------------------------------------
// dpe[b,f] = dh[b,:]@Wd[:,f] + bd + be, paired with Wa
// ---------------------------------------------------------------------------
__global__ void k_decproj(const float* __restrict__ dh, const float* __restrict__ Wd,
                          const float* __restrict__ bd, const float* __restrict__ be,
                          const float* __restrict__ Wa) {
    int b = blockIdx.x, f = threadIdx.x;
    __shared__ float sdh[DEC_];
    for (int d = f; d < DEC_; d += ENC_) sdh[d] = dh[b * DEC_ + d];
    __syncthreads();
    float acc = bd[f] + be[f];
#pragma unroll 8
    for (int d = 0; d < DEC_; ++d) acc += sdh[d] * Wd[d * ENC_ + f];
    g_dw[b * ENC_ + f] = make_float2(acc, Wa[f]);
}

// ---------------------------------------------------------------------------
// k_scores: 64-row compacted tile x 256 cols, fp16 HMMA + tanh*Wa epilogue
// ---------------------------------------------------------------------------
static __device__ __forceinline__ void loadB(unsigned sb, int c, int tid) {
#pragma unroll
    for (int i = 0; i < 4; ++i) {
        int slot = tid + i * 256;
        cp16(sb + OBI(c & 1) + (unsigned)slot * 16u, &g_Bt[c][slot * 16]);
    }
    CP_COMMIT();
}
static __device__ __forceinline__ void cvtstore(unsigned dst, float4 v0, float4 v1) {
    float vf[8] = {v0.x, v0.y, v0.z, v0.w, v1.x, v1.y, v1.z, v1.w};
    unsigned hu[4];
#pragma unroll
    for (int q = 0; q < 4; ++q) {
        __half2 hp = __halves2half2(__float2half_rn(vf[2 * q]),
                                    __float2half_rn(vf[2 * q + 1]));
        hu[q] = *(unsigned*)&hp;
    }
    asm volatile("st.shared.v4.b32 [%0], {%1,%2,%3,%4};"
                 :: "r"(dst), "r"(hu[0]), "r"(hu[1]), "r"(hu[2]), "r"(hu[3]));
}

__global__ __launch_bounds__(256, 2)
void k_scores(const float* __restrict__ enc) {
    const int b = blockIdx.x >> 6, tt = blockIdx.x & 63;
    const int cnt = g_cnt[b];
    if (tt * MT >= cnt) return;                       // inactive tile: fast exit

    extern __shared__ __align__(16) unsigned char sm[];
    const unsigned sb = s2u(sm);
    const int tid = threadIdx.x, lane = tid & 31, w = tid >> 5;
    const int wr = w & 1, wc = w >> 1;

    // this thread's A slice: compacted row j -> real row g_idx, bytes [s_*32..)
    const int r_ = tid >> 2, s_ = tid & 3;
    const int j = tt * MT + r_;
    const int row = g_idx[b * S_ + min(j, cnt - 1)];
    const float4* ap = (const float4*)(enc + ((size_t)b * S_ + row) * 256 + s_ * 8);
    const unsigned adst = (unsigned)(((r_ >> 4) * 2 + (s_ >> 1)) * 512 +
                                     (s_ & 1) * 256 + (r_ & 15) * 16);

    loadB(sb, 0, tid);
    ((float2*)(sm + ODW))[tid] = g_dw[b * 256 + tid];

    float4 r0 = ap[0], r1 = ap[1];
    cvtstore(sb + OAI(0) + adst, r0, r1);
    CP_WAIT0();

    float acc[2][8][4];
#pragma unroll
    for (int mi = 0; mi < 2; ++mi)
#pragma unroll
        for (int ni = 0; ni < 8; ++ni)
#pragma unroll
            for (int q = 0; q < 4; ++q) acc[mi][ni][q] = 0.f;

    const unsigned a_lo = (unsigned)((lane & 15) * 16 + (lane >> 4) * 256);
    const unsigned b_lo = (unsigned)((lane & 7) * 16 + ((lane >> 4) & 1) * 128 +
                                     ((lane >> 3) & 1) * 256);

#pragma unroll 1
    for (int c = 0; c < 8; ++c) {
        const int buf = c & 1;
        __syncthreads();
        if (c < 7) {
            loadB(sb, c + 1, tid);
            r0 = ap[(c + 1) * 8];
            r1 = ap[(c + 1) * 8 + 1];
        }
        const unsigned ah_b = sb + OAI(buf) + a_lo;
        const unsigned bh_b = sb + OBI(buf) + b_lo;
#pragma unroll
        for (int ks = 0; ks < 2; ++ks) {
            unsigned af[2][4], bh[8][2];
#pragma unroll
            for (int mi = 0; mi < 2; ++mi)
                LDM4(af[mi], ah_b + (unsigned)(((wr * 2 + mi) * 2 + ks) * 512));
#pragma unroll
            for (int p = 0; p < 4; ++p) {
                const unsigned blk = (unsigned)(((wc * 4 + p) * 2 + ks) * 512);
                unsigned r4[4];
                LDM4(r4, bh_b + blk);
                bh[2 * p][0] = r4[0]; bh[2 * p][1] = r4[1];
                bh[2 * p + 1][0] = r4[2]; bh[2 * p + 1][1] = r4[3];
            }
#pragma unroll
            for (int mi = 0; mi < 2; ++mi)
#pragma unroll
                for (int ni = 0; ni < 8; ++ni)
                    MMAH(acc[mi][ni], af[mi], bh[ni][0], bh[ni][1]);
        }
        if (c < 7) {
            cvtstore(sb + OAI(buf ^ 1) + adst, r0, r1);
            CP_WAIT0();
        }
    }

    // Epilogue: partial scores = sum_cols Wa * tanh(dpe + v)
    const float2* sdw = (const float2*)(sm + ODW);
    float* red = (float*)(sm + OBI(0));
#pragma unroll
    for (int mi = 0; mi < 2; ++mi) {
        float p0 = 0.f, p1 = 0.f;
#pragma unroll
        for (int ni = 0; ni < 8; ++ni) {
            int cc = wc * 64 + ni * 8 + 2 * (lane & 3);
            float2 w0 = sdw[cc], w1 = sdw[cc + 1];
            p0 += w0.y * tanha(acc[mi][ni][0] + w0.x) +
                  w1.y * tanha(acc[mi][ni][1] + w1.x);
            p1 += w0.y * tanha(acc[mi][ni][2] + w0.x) +
                  w1.y * tanha(acc[mi][ni][3] + w1.x);
        }
        p0 += __shfl_xor_sync(~0u, p0, 1); p0 += __shfl_xor_sync(~0u, p0, 2);
        p1 += __shfl_xor_sync(~0u, p1, 1); p1 += __shfl_xor_sync(~0u, p1, 2);
        if ((lane & 3) == 0) {
            int r = wr * 32 + mi * 16 + (lane >> 2);
            red[r * 5 + wc] = p0;
            red[(r + 8) * 5 + wc] = p1;
        }
    }
    __syncthreads();
    if (tid < MT && tt * MT + tid < cnt) {
        float s = red[tid * 5] + red[tid * 5 + 1] + red[tid * 5 + 2] + red[tid * 5 + 3];
        g_scores[b * S_ + tt * MT + tid] = s;
    }
}

// ---------------------------------------------------------------------------
// Softmax over compacted scores; scatter to attn output + compacted copy
// ---------------------------------------------------------------------------
__global__ void k_softmax(float* __restrict__ attn) {
    const int b = blockIdx.x, t = threadIdx.x;        // 1024 threads
    const int cnt = g_cnt[b];
    const float* sc = g_scores + b * S_;
    float v[4], mx = -INFINITY;
#pragma unroll
    for (int i = 0; i < 4; ++i) {
        int j = t + i * 1024;
        v[i] = (j < cnt) ? sc[j] : -INFINITY;
        mx = fmaxf(mx, v[i]);
    }
    __shared__ float rb[32];
    for (int o = 16; o; o >>= 1) mx = fmaxf(mx, __shfl_xor_sync(~0u, mx, o));
    if ((t & 31) == 0) rb[t >> 5] = mx;
    __syncthreads();
    if (t < 32) {
        float m2 = rb[t];
        for (int o = 16; o; o >>= 1) m2 = fmaxf(m2, __shfl_xor_sync(~0u, m2, o));
        rb[t] = m2;
    }
    __syncthreads();
    mx = rb[0];
    __syncthreads();
    float e[4], tot = 0.f;
#pragma unroll
    for (int i = 0; i < 4; ++i) { e[i] = expf(v[i] - mx); tot += e[i]; }
    for (int o = 16; o; o >>= 1) tot += __shfl_xor_sync(~0u, tot, o);
    if ((t & 31) == 0) rb[t >> 5] = tot;
    __syncthreads();
    if (t < 32) {
        float s2 = rb[t];
        for (int o = 16; o; o >>= 1) s2 += __shfl_xor_sync(~0u, s2, o);
        rb[t] = s2;
    }
    __syncthreads();
    const float inv = 1.f / rb[0];
#pragma unroll
    for (int i = 0; i < 4; ++i) {
        int j = t + i * 1024;
        if (j < cnt) {
            float a = e[i] * inv;
            attn[b * S_ + g_idx[b * S_ + j]] = a;
            g_attnc[b * S_ + j] = a;
        }
    }
}

// ---------------------------------------------------------------------------
// Context over compacted rows: 8 segments x 64 batches + reduce
// ---------------------------------------------------------------------------
__global__ void k_context(const float* __restrict__ enc) {
    const int seg = blockIdx.x & 7, b = blockIdx.x >> 3, t = threadIdx.x;
    const int c4 = t & 63, sg = t >> 6;
    const int cnt = g_cnt[b];
    const int s0 = seg * 512;
    __shared__ int   sidx[512];
    __shared__ float sat[512];
    for (int i = t; i < 512; i += 256) {
        int j = s0 + i;
        if (j < cnt) { sidx[i] = g_idx[b * S_ + j]; sat[i] = g_attnc[b * S_ + j]; }
        else         { sidx[i] = 0;                 sat[i] = 0.f; }
    }
    __syncthreads();
    const float4* e4 = (const float4*)enc + (size_t)b * S_ * 64;
    float4 acc = make_float4(0.f, 0.f, 0.f, 0.f);
    const int lim = min(512, cnt - s0);               // may be <=0
#pragma unroll 4
    for (int i = sg; i < lim; i += 4) {
        float a = sat[i];
        float4 e = e4[(size_t)sidx[i] * 64 + c4];
        acc.x += a * e.x; acc.y += a * e.y; acc.z += a * e.z; acc.w += a * e.w;
    }
    __shared__ float4 sr[4][64];
    sr[sg][c4] = acc;
    __syncthreads();
    if (t < 64) {
        float4 r = sr[0][t];
#pragma unroll
        for (int g = 1; g < 4; ++g) {
            float4 q = sr[g][t];
            r.x += q.x; r.y += q.y; r.z += q.z; r.w += q.w;
        }
        ((float4*)g_cpart)[(b * 8 + seg) * 64 + t] = r;
    }
}
__global__ void k_cred(float* __restrict__ ctx) {
    const int b = blockIdx.x, t = threadIdx.x;
    const float4* p = (const float4*)g_cpart;
    float4 r = make_float4(0.f, 0.f, 0.f, 0.f);
#pragma unroll
    for (int seg = 0; seg < 8; ++seg) {
        float4 q = p[(b * 8 + seg) * 64 + t];
        r.x += q.x; r.y += q.y; r.z += q.z; r.w += q.w;
    }
    ((float4*)ctx)[b * 64 + t] = r;
}

// ---------------------------------------------------------------------------
extern "C" void kernel_launch(void* const* d_in, const int* in_sizes, int n_in,
                              void* d_out, int out_size) {
    const float* dh   = (const float*)d_in[0];
    const float* enc  = (const float*)d_in[1];
    const int*   mask = (const int*)  d_in[2];
    const float* Wd   = (const float*)d_in[3];
    const float* bd   = (const float*)d_in[4];
    const float* We   = (const float*)d_in[5];
    const float* be   = (const float*)d_in[6];
    const float* Wa   = (const float*)d_in[7];
    // d_in[8] = ba: uniform shift on scores, cancels in softmax

    float* out  = (float*)d_out;
    float* ctx  = out;
    float* attn = out + B_ * ENC_;

    cudaFuncSetAttribute(k_scores, cudaFuncAttributeMaxDynamicSharedMemorySize, SMEM_BYTES);

    k_prep<<<256, 256>>>(We);
    k_compact<<<B_, 1024>>>(mask, attn);
    k_decproj<<<B_, ENC_>>>(dh, Wd, bd, be, Wa);
    k_scores<<<B_ * 64, 256, SMEM_BYTES>>>(enc);
    k_softmax<<<B_, 1024>>>(attn);
    k_context<<<8 * B_, 256>>>(enc);
    k_cred<<<B_, 64>>>(ctx);
}

// round 12
// speedup vs baseline: 3.7328x; 1.5813x over previous
#include <cuda_runtime.h>
#include <cuda_fp16.h>
#include <math.h>

#define B_   64
#define S_   4096
#define DEC_ 512
#define ENC_ 256
#define MT   64                                        // rows per k_scores tile

// ---------------- device scratch (allocation-free rule) ----------------
__device__ float2 g_dw[B_ * ENC_];                    // (dpe, Wa) per (b,f)
__device__ float  g_scores[B_ * S_];                  // compacted e = exp(score)
__device__ int    g_idx[B_ * S_];                     // unmasked index lists
__device__ int    g_cnt[B_];                          // unmasked counts
__device__ float  g_cpart[(size_t)B_ * 64 * ENC_];    // per-tile ctx partials (16MB)
__device__ float  g_esum[B_ * 64];                    // per-tile sum of e
// We^T fp16 per K-chunk, LDSM-native block layout:
//   addr(n,kc) = (g*2+ks)*512 + h16*256 + (n&15)*16 + (kc&7)*2
__device__ __align__(16) unsigned char g_Bt[8][16384];

// ---------------- smem layout (bytes), per CTA = 43520 ----------------
#define OBI(buf)     ((unsigned)(buf) * 16384u)        // B fp16, 32K dbuf (buf0 reused: red)
#define OAI(buf)     (32768u + (unsigned)(buf) * 4096u) // A fp16 img (reused: sr)
#define ODW          40960u                            // float2[256]
#define OSIDX        43008u                            // int[64] row indices
#define OSE          43264u                            // float[64] e values
#define SMEM_BYTES   43520u

static __device__ __forceinline__ unsigned s2u(const void* p) {
    unsigned a;
    asm("{ .reg .u64 t; cvta.to.shared.u64 t, %1; cvt.u32.u64 %0, t; }" : "=r"(a) : "l"(p));
    return a;
}
static __device__ __forceinline__ void cp16(unsigned dst, const void* src) {
    asm volatile("cp.async.cg.shared.global [%0], [%1], 16;" :: "r"(dst), "l"(src));
}
#define CP_COMMIT() asm volatile("cp.async.commit_group;" ::: "memory")
#define CP_WAIT0()  asm volatile("cp.async.wait_group 0;" ::: "memory")

#define LDM4(r, addr) \
    asm volatile("ldmatrix.sync.aligned.m8n8.x4.shared.b16 {%0,%1,%2,%3}, [%4];" \
        : "=r"((r)[0]), "=r"((r)[1]), "=r"((r)[2]), "=r"((r)[3]) : "r"(addr))

#define MMAH(d, a, b0, b1) \
    asm volatile("mma.sync.aligned.m16n8k16.row.col.f32.f16.f16.f32 " \
        "{%0,%1,%2,%3}, {%4,%5,%6,%7}, {%8,%9}, {%0,%1,%2,%3};" \
        : "+f"((d)[0]), "+f"((d)[1]), "+f"((d)[2]), "+f"((d)[3]) \
        : "r"((a)[0]), "r"((a)[1]), "r"((a)[2]), "r"((a)[3]), "r"(b0), "r"(b1))

static __device__ __forceinline__ float tanha(float x) {
    float y;
    asm("tanh.approx.f32 %0, %1;" : "=f"(y) : "f"(x));
    return y;
}

// ---------------------------------------------------------------------------
// k_pre: 3 roles. blocks 0-63: compact+zero attn; 64-127: We prep; 128-191: decproj
// ---------------------------------------------------------------------------
__global__ __launch_bounds__(1024)
void k_pre(const int* __restrict__ mask, float* __restrict__ attn,
           const float* __restrict__ We,
           const float* __restrict__ dh, const float* __restrict__ Wd,
           const float* __restrict__ bd, const float* __restrict__ be,
           const float* __restrict__ Wa) {
    const int bid = blockIdx.x, t = threadIdx.x;
    if (bid < 64) {                                   // ---- compact ----
        const int b = bid;
        const int4 m = ((const int4*)(mask + b * S_))[t];
        int c0 = m.x != 0, c1 = m.y != 0, c2 = m.z != 0, c3 = m.w != 0;
        const int ls = c0 + c1 + c2 + c3;
        const int lane = t & 31, wid = t >> 5;
        int ws = ls;
#pragma unroll
        for (int o = 1; o < 32; o <<= 1) {
            int v = __shfl_up_sync(~0u, ws, o);
            if (lane >= o) ws += v;
        }
        __shared__ int wsum[32];
        if (lane == 31) wsum[wid] = ws;
        __syncthreads();
        if (t < 32) {
            int v = wsum[t];
#pragma unroll
            for (int o = 1; o < 32; o <<= 1) {
                int u = __shfl_up_sync(~0u, v, o);
                if (t >= o) v += u;
            }
            wsum[t] = v;
        }
        __syncthreads();
        int p = (wid ? wsum[wid - 1] : 0) + (ws - ls);
        const int s = t * 4;
        int* gi = g_idx + b * S_;
        float* at = attn + b * S_;
        if (c0) gi[p++] = s;     else at[s]     = 0.f;
        if (c1) gi[p++] = s + 1; else at[s + 1] = 0.f;
        if (c2) gi[p++] = s + 2; else at[s + 2] = 0.f;
        if (c3) gi[p++] = s + 3; else at[s + 3] = 0.f;
        if (t == 1023) g_cnt[b] = p;
    } else if (bid < 128) {                           // ---- We prep ----
        const int k = (bid - 64) * 4 + (t >> 8), n = t & 255;
        float v = We[k * 256 + n];
        int ch = k >> 5, kc = k & 31;
        int g = n >> 4, ks = kc >> 4, h16 = (kc >> 3) & 1;
        unsigned addr = (unsigned)((g * 2 + ks) * 512 + h16 * 256 + (n & 15) * 16 +
                                   (kc & 7) * 2);
        *(__half*)&g_Bt[ch][addr] = __float2half_rn(v);
    } else {                                          // ---- decproj ----
        const int b = bid - 128;
        __shared__ float sdh[DEC_];
        __shared__ float part[4][256];
        if (t < DEC_) sdh[t] = dh[b * DEC_ + t];
        __syncthreads();
        const int f = t & 255, q = t >> 8;
        float acc = 0.f;
#pragma unroll 8
        for (int d = q * 128; d < q * 128 + 128; ++d) acc += sdh[d] * Wd[d * 256 + f];
        part[q][f] = acc;
        __syncthreads();
        if (t < 256) {
            float v = part[0][t] + part[1][t] + part[2][t] + part[3][t] + bd[t] + be[t];
            g_dw[b * 256 + t] = make_float2(v, Wa[t]);
        }
    }
}

// ---------------------------------------------------------------------------
// k_scores: 64-row compacted tile, fp16 HMMA + fused tanh/exp/context epilogue
// ---------------------------------------------------------------------------
static __device__ __forceinline__ void loadB(unsigned sb, int c, int tid) {
#pragma unroll
    for (int i = 0; i < 4; ++i) {
        int slot = tid + i * 256;
        cp16(sb + OBI(c & 1) + (unsigned)slot * 16u, &g_Bt[c][slot * 16]);
    }
    CP_COMMIT();
}
static __device__ __forceinline__ void cvtstore(unsigned dst, float4 v0, float4 v1) {
    float vf[8] = {v0.x, v0.y, v0.z, v0.w, v1.x, v1.y, v1.z, v1.w};
    unsigned hu[4];
#pragma unroll
    for (int q = 0; q < 4; ++q) {
        __half2 hp = __halves2half2(__float2half_rn(vf[2 * q]),
                                    __float2half_rn(vf[2 * q + 1]));
        hu[q] = *(unsigned*)&hp;
    }
    asm volatile("st.shared.v4.b32 [%0], {%1,%2,%3,%4};"
                 :: "r"(dst), "r"(hu[0]), "r"(hu[1]), "r"(hu[2]), "r"(hu[3]));
}

__global__ __launch_bounds__(256, 2)
void k_scores(const float* __restrict__ enc) {
    const int b = blockIdx.x >> 6, tt = blockIdx.x & 63;
    const int cnt = g_cnt[b];
    const int tid = threadIdx.x;
    if (tt * MT >= cnt) {                             // inactive: zero partials
        if (tid < 64) {
            float4 z = make_float4(0.f, 0.f, 0.f, 0.f);
            ((float4*)g_cpart)[((size_t)b * 64 + tt) * 64 + tid] = z;
        }
        if (tid == 0) g_esum[b * 64 + tt] = 0.f;
        return;
    }

    extern __shared__ __align__(16) unsigned char sm[];
    const unsigned sb = s2u(sm);
    const int lane = tid & 31, w = tid >> 5;
    const int wr = w & 1, wc = w >> 1;

    const int r_ = tid >> 2, s_ = tid & 3;
    const int j = tt * MT + r_;
    const int row = g_idx[b * S_ + min(j, cnt - 1)];
    const float4* ap = (const float4*)(enc + ((size_t)b * S_ + row) * 256 + s_ * 8);
    const unsigned adst = (unsigned)(((r_ >> 4) * 2 + (s_ >> 1)) * 512 +
                                     (s_ & 1) * 256 + (r_ & 15) * 16);
    if ((tid & 3) == 0) ((int*)(sm + OSIDX))[r_] = row;

    loadB(sb, 0, tid);
    ((float2*)(sm + ODW))[tid] = g_dw[b * 256 + tid];

    float4 r0 = ap[0], r1 = ap[1];
    cvtstore(sb + OAI(0) + adst, r0, r1);
    CP_WAIT0();

    float acc[2][8][4];
#pragma unroll
    for (int mi = 0; mi < 2; ++mi)
#pragma unroll
        for (int ni = 0; ni < 8; ++ni)
#pragma unroll
            for (int q = 0; q < 4; ++q) acc[mi][ni][q] = 0.f;

    const unsigned a_lo = (unsigned)((lane & 15) * 16 + (lane >> 4) * 256);
    const unsigned b_lo = (unsigned)((lane & 7) * 16 + ((lane >> 4) & 1) * 128 +
                                     ((lane >> 3) & 1) * 256);

#pragma unroll 1
    for (int c = 0; c < 8; ++c) {
        const int buf = c & 1;
        __syncthreads();
        if (c < 7) {
            loadB(sb, c + 1, tid);
            r0 = ap[(c + 1) * 8];
            r1 = ap[(c + 1) * 8 + 1];
        }
        const unsigned ah_b = sb + OAI(buf) + a_lo;
        const unsigned bh_b = sb + OBI(buf) + b_lo;
#pragma unroll
        for (int ks = 0; ks < 2; ++ks) {
            unsigned af[2][4], bh[8][2];
#pragma unroll
            for (int mi = 0; mi < 2; ++mi)
                LDM4(af[mi], ah_b + (unsigned)(((wr * 2 + mi) * 2 + ks) * 512));
#pragma unroll
            for (int p = 0; p < 4; ++p) {
                const unsigned blk = (unsigned)(((wc * 4 + p) * 2 + ks) * 512);
                unsigned r4[4];
                LDM4(r4, bh_b + blk);
                bh[2 * p][0] = r4[0]; bh[2 * p][1] = r4[1];
                bh[2 * p + 1][0] = r4[2]; bh[2 * p + 1][1] = r4[3];
            }
#pragma unroll
            for (int mi = 0; mi < 2; ++mi)
#pragma unroll
                for (int ni = 0; ni < 8; ++ni)
                    MMAH(acc[mi][ni], af[mi], bh[ni][0], bh[ni][1]);
        }
        if (c < 7) {
            cvtstore(sb + OAI(buf ^ 1) + adst, r0, r1);
            CP_WAIT0();
        }
    }

    // ---- Epilogue 1: score partials = sum_cols Wa * tanh(dpe + v) ----
    const float2* sdw = (const float2*)(sm + ODW);
    float* red = (float*)(sm + OBI(0));
#pragma unroll
    for (int mi = 0; mi < 2; ++mi) {
        float p0 = 0.f, p1 = 0.f;
#pragma unroll
        for (int ni = 0; ni < 8; ++ni) {
            int cc = wc * 64 + ni * 8 + 2 * (lane & 3);
            float2 w0 = sdw[cc], w1 = sdw[cc + 1];
            p0 += w0.y * tanha(acc[mi][ni][0] + w0.x) +
                  w1.y * tanha(acc[mi][ni][1] + w1.x);
            p1 += w0.y * tanha(acc[mi][ni][2] + w0.x) +
                  w1.y * tanha(acc[mi][ni][3] + w1.x);
        }
        p0 += __shfl_xor_sync(~0u, p0, 1); p0 += __shfl_xor_sync(~0u, p0, 2);
        p1 += __shfl_xor_sync(~0u, p1, 1); p1 += __shfl_xor_sync(~0u, p1, 2);
        if ((lane & 3) == 0) {
            int r = wr * 32 + mi * 16 + (lane >> 2);
            red[r * 5 + wc] = p0;
            red[(r + 8) * 5 + wc] = p1;
        }
    }
    __syncthreads();
    // ---- Epilogue 2: e = exp(score) (safe: |score| <= ~13), store ----
    float* se = (float*)(sm + OSE);
    if (tid < MT) {
        float s = red[tid * 5] + red[tid * 5 + 1] + red[tid * 5 + 2] + red[tid * 5 + 3];
        float e = (tt * MT + tid < cnt) ? __expf(s) : 0.f;
        se[tid] = e;
        g_scores[b * S_ + tt * MT + tid] = e;
    }
    __syncthreads();
    if (tid < 32) {                                   // tile sum of e
        float v = se[tid] + se[tid + 32];
#pragma unroll
        for (int o = 16; o; o >>= 1) v += __shfl_xor_sync(~0u, v, o);
        if (tid == 0) g_esum[b * 64 + tt] = v;
    }
    // ---- Epilogue 3: ctx partial = sum_r e[r] * enc[row_r, :] (L2 hits) ----
    {
        const int c4 = tid & 63, rg = tid >> 6;
        const int* sidx = (const int*)(sm + OSIDX);
        const float4* e4 = (const float4*)enc + (size_t)b * S_ * 64;
        float4 a4 = make_float4(0.f, 0.f, 0.f, 0.f);
#pragma unroll 4
        for (int i = 0; i < 16; ++i) {
            int r = rg * 16 + i;
            float wv = se[r];
            float4 ev = e4[(size_t)sidx[r] * 64 + c4];
            a4.x += wv * ev.x; a4.y += wv * ev.y; a4.z += wv * ev.z; a4.w += wv * ev.w;
        }
        float4* sr = (float4*)(sm + OAI(0));
        sr[rg * 64 + c4] = a4;
        __syncthreads();
        if (tid < 64) {
            float4 q0 = sr[tid], q1 = sr[64 + tid], q2 = sr[128 + tid], q3 = sr[192 + tid];
            float4 o;
            o.x = q0.x + q1.x + q2.x + q3.x;
            o.y = q0.y + q1.y + q2.y + q3.y;
            o.z = q0.z + q1.z + q2.z + q3.z;
            o.w = q0.w + q1.w + q2.w + q3.w;
            ((float4*)g_cpart)[((size_t)b * 64 + tt) * 64 + tid] = o;
        }
    }
}

// ---------------------------------------------------------------------------
// k_finish: per batch: sum tiles -> ctx = acc/sum; attn scatter = e/sum
// ---------------------------------------------------------------------------
__global__ __launch_bounds__(1024)
void k_finish(float* __restrict__ ctx, float* __restrict__ attn) {
    const int b = blockIdx.x, t = threadIdx.x;
    __shared__ float s_e[64];
    __shared__ float s_inv;
    if (t < 64) s_e[t] = g_esum[b * 64 + t];
    __syncthreads();
    if (t < 32) {
        float v = s_e[t] + s_e[t + 32];
#pragma unroll
        for (int o = 16; o; o >>= 1) v += __shfl_xor_sync(~0u, v, o);
        if (t == 0) s_inv = 1.f / v;
    }
    __syncthreads();
    const float inv = s_inv;
    if (t < 256) {
        float acc = 0.f;
#pragma unroll 8
        for (int tt = 0; tt < 64; ++tt)
            acc += g_cpart[((size_t)b * 64 + tt) * 256 + t];
        ctx[b * 256 + t] = acc * inv;
    }
    const int cnt = g_cnt[b];
    for (int j = t; j < cnt; j += 1024)
        attn[b * S_ + g_idx[b * S_ + j]] = g_scores[b * S_ + j] * inv;
}

// ---------------------------------------------------------------------------
extern "C" void kernel_launch(void* const* d_in, const int* in_sizes, int n_in,
                              void* d_out, int out_size) {
    const float* dh   = (const float*)d_in[0];
    const float* enc  = (const float*)d_in[1];
    const int*   mask = (const int*)  d_in[2];
    const float* Wd   = (const float*)d_in[3];
    const float* bd   = (const float*)d_in[4];
    const float* We   = (const float*)d_in[5];
    const float* be   = (const float*)d_in[6];
    const float* Wa   = (const float*)d_in[7];
    // d_in[8] = ba: uniform shift on scores, cancels in softmax

    float* out  = (float*)d_out;
    float* ctx  = out;
    float* attn = out + B_ * ENC_;

    cudaFuncSetAttribute(k_scores, cudaFuncAttributeMaxDynamicSharedMemorySize, SMEM_BYTES);

    k_pre<<<192, 1024>>>(mask, attn, We, dh, Wd, bd, be, Wa);
    k_scores<<<B_ * 64, 256, SMEM_BYTES>>>(enc);
    k_finish<<<B_, 1024>>>(ctx, attn);
}